// round 1
// baseline (speedup 1.0000x reference)
#include <cuda_runtime.h>
#include <math.h>

constexpr int NAT = 64;     // atoms per molecule
constexpr int NE  = 512;    // edges per molecule
constexpr int NA  = 65;     // NAT + 1 (charge-conservation row)
constexpr int NUMEL = 10;
constexpr int WP = 513;     // W row pitch (conflict-free)
constexpr int HP = 66;      // H row pitch
constexpr int KP = 67;      // K row pitch (65 cols + 1 aug + pad)

// ---- shared memory byte offsets ----
constexpr int OFF_HD  = 0;                      // double hd[65]
constexpr int OFF_WD  = OFF_HD + 65 * 8;        // double wd[65]
constexpr int OFF_CWD = OFF_WD + 65 * 8;        // double cwd[65]
constexpr int OFF_W   = 1600;                   // float W[65][513]
constexpr int OFF_AS  = OFF_W  + NA * WP * 4;   // float A[64][64]
constexpr int OFF_HS  = OFF_AS + NAT * NAT * 4; // float H[65][66]
constexpr int OFF_KM  = OFF_HS + NA * HP * 4;   // float K[65][67]
constexpr int OFF_SG  = OFF_KM + NA * KP * 4;   // float sg[512]
constexpr int OFF_SA  = OFF_SG + NE * 4;        // float s[512]
constexpr int OFF_PX  = OFF_SA + NE * 4;        // float px[64]
constexpr int OFF_PY  = OFF_PX + NAT * 4;
constexpr int OFF_PZ  = OFF_PY + NAT * 4;
constexpr int OFF_EN  = OFF_PZ + NAT * 4;       // eneg[64]
constexpr int OFF_DG  = OFF_EN + NAT * 4;       // diag[64]
constexpr int OFF_RR  = OFF_DG + NAT * 4;       // sigma = r*r [64]
constexpr int OFF_RF  = OFF_RR + NAT * 4;       // float rf[68]
constexpr int OFF_PIV = OFF_RF + 68 * 4;        // int piv[68]
constexpr int SMEM_BYTES = OFF_PIV + 68 * 4;    // ~192 KB

__global__ __launch_bounds__(256, 1)
void cheq_kernel(const float* __restrict__ positions,
                 const float* __restrict__ T,
                 const float* __restrict__ eneg,
                 const float* __restrict__ node_attrs,
                 const float* __restrict__ total_charge,
                 const float* __restrict__ hardness,
                 const float* __restrict__ cov_radii,
                 const int*   __restrict__ atomic_numbers,
                 const int*   __restrict__ edge_index,
                 float* __restrict__ out)
{
    extern __shared__ __align__(16) unsigned char sm[];
    double* hd  = (double*)(sm + OFF_HD);
    double* wd  = (double*)(sm + OFF_WD);
    double* cwd = (double*)(sm + OFF_CWD);
    float* W   = (float*)(sm + OFF_W);
    float* As  = (float*)(sm + OFF_AS);
    float* Hs  = (float*)(sm + OFF_HS);
    float* Km  = (float*)(sm + OFF_KM);
    float* sg  = (float*)(sm + OFF_SG);
    float* sa  = (float*)(sm + OFF_SA);
    float* px  = (float*)(sm + OFF_PX);
    float* py  = (float*)(sm + OFF_PY);
    float* pz  = (float*)(sm + OFF_PZ);
    float* ens = (float*)(sm + OFF_EN);
    float* dgs = (float*)(sm + OFF_DG);
    float* rrs = (float*)(sm + OFF_RR);
    float* rf  = (float*)(sm + OFF_RF);
    int*   piv = (int*)(sm + OFF_PIV);

    const int mol = blockIdx.x;
    const int t = threadIdx.x;
    const float* Tm = T + (size_t)mol * (NAT * NE);
    const float* pm = positions + mol * NAT * 3;
    const int* eim = edge_index + mol * 2 * NE;
    const float q = total_charge[mol];

    // ---- per-atom small loads ----
    if (t < NAT) {
        px[t] = pm[3*t+0]; py[t] = pm[3*t+1]; pz[t] = pm[3*t+2];
        ens[t] = eneg[mol * NAT + t];
        float r = cov_radii[atomic_numbers[mol * NAT + t]];
        rrs[t] = r * r;
        const float* na = node_attrs + (size_t)(mol * NAT + t) * NUMEL;
        float best = na[0]; int bi = 0;
        #pragma unroll
        for (int j = 1; j < NUMEL; j++) { float v = na[j]; if (v > best) { best = v; bi = j; } }
        dgs[t] = hardness[bi] + 0.5641895835477563f / r;   // 1/sqrt(pi)/r
    }
    __syncthreads();

    // ---- A matrix (64x64) ----
    for (int idx = t; idx < NAT * NAT; idx += 256) {
        int i = idx >> 6, j = idx & 63;
        float v;
        if (i == j) v = dgs[i];
        else {
            float dx = px[i]-px[j], dy = py[i]-py[j], dz = pz[i]-pz[j];
            float d = sqrtf(dx*dx + dy*dy + dz*dz);
            float arg = d * rsqrtf(2.0f * (rrs[i] + rrs[j]));
            v = erff(arg) / d;
        }
        As[idx] = v;
    }

    // ---- edges: cut diagonal, scale s=sqrt(1/cut), b = -T^T eneg, sg = s*(b - q) ----
    for (int e = t; e < NE; e += 256) {
        int a0 = eim[e], a1 = eim[NE + e];
        float dx = px[a0]-px[a1], dy = py[a0]-py[a1], dz = pz[a0]-pz[a1];
        float ed = sqrtf(dx*dx + dy*dy + dz*dz);
        float th = 0.15707963267948966f * ed;   // pi*ed/(2*r_cut), r_cut=10
        float sh = sinf(0.5f * th);
        float ct = cosf(th);
        // cut = 1/cos - 1 = 2 sin^2(t/2)/cos(t)  (cancellation-free); dinv = 1/cut
        float dinv = ct / (2.0f * sh * sh);
        dinv = fmaxf(dinv, 1e-30f);
        float s = sqrtf(dinv);
        sa[e] = s;
        W[64 * WP + e] = s;                      // ones-row of V, scaled
        float acc = 0.f;
        #pragma unroll 8
        for (int n = 0; n < NAT; n++) acc = fmaf(Tm[n * NE + e], ens[n], acc);
        sg[e] = s * (-acc - q);
    }
    __syncthreads();

    // ---- W rows 0..63 = T scaled by s (vectorized global read) ----
    {
        const float4* T4 = (const float4*)Tm;
        for (int idx = t; idx < NAT * (NE / 4); idx += 256) {
            int a = idx >> 7, e4 = idx & 127;
            float4 v = T4[idx];
            int e = e4 * 4;
            float* wr = W + a * WP + e;
            wr[0] = v.x * sa[e];   wr[1] = v.y * sa[e+1];
            wr[2] = v.z * sa[e+2]; wr[3] = v.w * sa[e+3];
        }
    }
    __syncthreads();

    // ---- H = W W^T (65x65), 16x16 threads x 5x5 register tiles (clamped overlap) ----
    {
        int tx = t & 15, ty = t >> 4;
        int a0 = ty * 5; if (a0 > NA - 5) a0 = NA - 5;
        int b0 = tx * 5; if (b0 > NA - 5) b0 = NA - 5;
        float acc[5][5];
        #pragma unroll
        for (int i = 0; i < 5; i++)
            #pragma unroll
            for (int j = 0; j < 5; j++) acc[i][j] = 0.f;
        const float* Wa = W + a0 * WP;
        const float* Wb = W + b0 * WP;
        for (int e = 0; e < NE; e += 2) {
            float ra0[5], ra1[5], rb0[5], rb1[5];
            #pragma unroll
            for (int i = 0; i < 5; i++) { ra0[i] = Wa[i*WP+e]; ra1[i] = Wa[i*WP+e+1]; }
            #pragma unroll
            for (int j = 0; j < 5; j++) { rb0[j] = Wb[j*WP+e]; rb1[j] = Wb[j*WP+e+1]; }
            #pragma unroll
            for (int i = 0; i < 5; i++)
                #pragma unroll
                for (int j = 0; j < 5; j++)
                    acc[i][j] = fmaf(ra1[i], rb1[j], fmaf(ra0[i], rb0[j], acc[i][j]));
        }
        #pragma unroll
        for (int i = 0; i < 5; i++)
            #pragma unroll
            for (int j = 0; j < 5; j++)
                Hs[(a0 + i) * HP + (b0 + j)] = acc[i][j];  // benign identical-value races
    }
    __syncthreads();

    // ---- h = W * sg (fp64 accumulate) ----
    {
        int w = t >> 5, lane = t & 31;
        for (int a = w; a < NA; a += 8) {
            const float* Wr = W + a * WP;
            double acc = 0.0;
            for (int e = lane; e < NE; e += 32) acc += (double)Wr[e] * (double)sg[e];
            #pragma unroll
            for (int off = 16; off; off >>= 1) acc += __shfl_down_sync(0xffffffffu, acc, off);
            if (lane == 0) hd[a] = acc;
        }
    }
    __syncthreads();

    // ---- K = I + H*C, C = blockdiag(A, -1); augmented col 65 = h ----
    for (int idx = t; idx < NA * NAT; idx += 256) {
        int a = idx >> 6, c = idx & 63;
        float acc = (a == c) ? 1.0f : 0.0f;
        const float* Hr = Hs + a * HP;
        const float* Ac = As + c;
        #pragma unroll 8
        for (int k = 0; k < NAT; k++) acc = fmaf(Hr[k], Ac[k * NAT], acc);
        Km[a * KP + c] = acc;
    }
    if (t < NA) {
        Km[t * KP + 64] = ((t == 64) ? 1.0f : 0.0f) - Hs[t * HP + 64];
        Km[t * KP + 65] = (float)hd[t];
    }
    __syncthreads();

    // ---- LU with partial pivoting on K[65][66] (col 65 = rhs) ----
    for (int k = 0; k < NA; k++) {
        if (t < 32) {
            float bv = -1.f; int bi = k;
            for (int i = k + t; i < NA; i += 32) {
                float v = fabsf(Km[i * KP + k]);
                if (v > bv) { bv = v; bi = i; }
            }
            #pragma unroll
            for (int off = 16; off; off >>= 1) {
                float ov = __shfl_down_sync(0xffffffffu, bv, off);
                int   oi = __shfl_down_sync(0xffffffffu, bi, off);
                if (ov > bv) { bv = ov; bi = oi; }
            }
            if (t == 0) piv[k] = bi;
        }
        __syncthreads();
        int p = piv[k];
        if (p != k) {
            for (int j = t; j < 66; j += 256) {
                float tmp = Km[k * KP + j]; Km[k * KP + j] = Km[p * KP + j]; Km[p * KP + j] = tmp;
            }
        }
        __syncthreads();
        float pinv = 1.0f / Km[k * KP + k];
        if (t > k && t < NA) Km[t * KP + k] *= pinv;
        __syncthreads();
        int ncols = 65 - k;               // cols k+1..65 inclusive
        int tot = (NA - 1 - k) * ncols;
        for (int idx = t; idx < tot; idx += 256) {
            int r = idx / ncols;
            int i = k + 1 + r;
            int j = k + 1 + (idx - r * ncols);
            Km[i * KP + j] = fmaf(-Km[i * KP + k], Km[k * KP + j], Km[i * KP + j]);
        }
        __syncthreads();
    }

    // ---- back substitution ----
    if (t < NA) rf[t] = Km[t * KP + 65];
    __syncthreads();
    for (int k = NA - 1; k >= 0; k--) {
        if (t == 0) rf[k] = rf[k] / Km[k * KP + k];
        __syncthreads();
        if (t < k) rf[t] = fmaf(-Km[t * KP + k], rf[k], rf[t]);
        __syncthreads();
    }
    if (t < NA) wd[t] = (double)rf[t];
    __syncthreads();

    // ---- 2x fp64-residual iterative refinement of (I + H C) w = h ----
    for (int it = 0; it < 2; it++) {
        int w = t >> 5, lane = t & 31;
        for (int kk = w; kk < NAT; kk += 8) {
            const float* Ar = As + kk * NAT;
            double acc = 0.0;
            for (int c = lane; c < NAT; c += 32) acc += (double)Ar[c] * wd[c];
            #pragma unroll
            for (int off = 16; off; off >>= 1) acc += __shfl_down_sync(0xffffffffu, acc, off);
            if (lane == 0) cwd[kk] = acc;
        }
        if (t == 0) cwd[64] = -wd[64];
        __syncthreads();
        for (int a = w; a < NA; a += 8) {
            const float* Hr = Hs + a * HP;
            double acc = 0.0;
            for (int k2 = lane; k2 < NA; k2 += 32) acc += (double)Hr[k2] * cwd[k2];
            #pragma unroll
            for (int off = 16; off; off >>= 1) acc += __shfl_down_sync(0xffffffffu, acc, off);
            if (lane == 0) rf[a] = (float)(hd[a] - wd[a] - acc);
        }
        __syncthreads();
        if (t == 0) {
            for (int k = 0; k < NA; k++) {
                int p = piv[k];
                if (p != k) { float tmp = rf[k]; rf[k] = rf[p]; rf[p] = tmp; }
            }
        }
        __syncthreads();
        for (int k = 0; k < NA - 1; k++) {       // forward (unit L)
            float rk = rf[k];
            if (t > k && t < NA) rf[t] = fmaf(-Km[t * KP + k], rk, rf[t]);
            __syncthreads();
        }
        for (int k = NA - 1; k >= 0; k--) {      // backward (U)
            if (t == 0) rf[k] = rf[k] / Km[k * KP + k];
            __syncthreads();
            if (t < k) rf[t] = fmaf(-Km[t * KP + k], rf[k], rf[t]);
            __syncthreads();
        }
        if (t < NA) wd[t] += (double)rf[t];
        __syncthreads();
    }

    // ---- y = V x = w; output first 64 entries ----
    if (t < NAT) out[mol * NAT + t] = (float)wd[t];
}

extern "C" void kernel_launch(void* const* d_in, const int* in_sizes, int n_in,
                              void* d_out, int out_size)
{
    const float* positions      = (const float*)d_in[0];
    const float* T              = (const float*)d_in[1];
    const float* eneg           = (const float*)d_in[2];
    const float* node_attrs     = (const float*)d_in[3];
    const float* total_charge   = (const float*)d_in[4];
    /* d_in[5] = p (unused) */
    const float* hardness       = (const float*)d_in[6];
    const float* cov_radii      = (const float*)d_in[7];
    const int*   atomic_numbers = (const int*)d_in[8];
    const int*   edge_index     = (const int*)d_in[9];
    float* out = (float*)d_out;

    int B = in_sizes[4];  // number of molecules
    cudaFuncSetAttribute(cheq_kernel, cudaFuncAttributeMaxDynamicSharedMemorySize, SMEM_BYTES);
    cheq_kernel<<<B, 256, SMEM_BYTES>>>(positions, T, eneg, node_attrs, total_charge,
                                        hardness, cov_radii, atomic_numbers, edge_index, out);
}

// round 2
// speedup vs baseline: 1.5619x; 1.5619x over previous
#include <cuda_runtime.h>
#include <math.h>

constexpr int NAT = 64;     // atoms per molecule
constexpr int NE  = 512;    // edges per molecule
constexpr int NA  = 65;     // NAT + 1
constexpr int NUMEL = 10;
constexpr int CH  = 256;    // W chunk width (edges)
constexpr int WCP = 260;    // Wc pitch (floats, /4 for float4)
constexpr int HP  = 68;     // Hs pitch (floats, /4)
constexpr int KP  = 67;     // Km pitch (floats)

// ---- shared memory byte offsets ----
constexpr int OFF_HD  = 0;                     // double hd[65]
constexpr int OFF_HDP = 528;                   // double hdp[130]
constexpr int OFF_WD  = 1568;                  // double wd[65]
constexpr int OFF_CWD = 2096;                  // double cwd[65]
constexpr int OFF_WC  = 2624;                  // float Wc[65][260]   (16B aligned)
constexpr int OFF_KM  = OFF_WC;                // float Km[65][67]    (aliases Wc)
constexpr int OFF_AS  = OFF_WC + 65*WCP*4;     // float As[64][64]    = 70224
constexpr int OFF_HS  = OFF_AS + 64*64*4;      // float Hs[65][68]    = 86608
constexpr int OFF_SA  = OFF_HS + 65*HP*4;      // float sa[512]       = 104288
constexpr int OFF_SG  = OFF_SA + 2048;         // float sg[512]
constexpr int OFF_PX  = OFF_SG + 2048;
constexpr int OFF_PY  = OFF_PX + 256;
constexpr int OFF_PZ  = OFF_PY + 256;
constexpr int OFF_EN  = OFF_PZ + 256;
constexpr int OFF_DG  = OFF_EN + 256;
constexpr int OFF_RR  = OFF_DG + 256;
constexpr int OFF_RF  = OFF_RR + 256;          // float rf[68]
constexpr int OFF_RG  = OFF_RF + 272;          // float rg[68]
constexpr int OFF_DI  = OFF_RG + 272;          // float dinv[68]
constexpr int OFF_PIV = OFF_DI + 272;          // int piv[68]
constexpr int OFF_PERM= OFF_PIV + 272;         // int perm[68]
constexpr int SMEM_BYTES = OFF_PERM + 272;     // 111280 B (~108.7 KB) -> 2 CTAs/SM

__global__ __launch_bounds__(256, 2)
void cheq_kernel(const float* __restrict__ positions,
                 const float* __restrict__ T,
                 const float* __restrict__ eneg,
                 const float* __restrict__ node_attrs,
                 const float* __restrict__ total_charge,
                 const float* __restrict__ hardness,
                 const float* __restrict__ cov_radii,
                 const int*   __restrict__ atomic_numbers,
                 const int*   __restrict__ edge_index,
                 float* __restrict__ out)
{
    extern __shared__ __align__(16) unsigned char sm[];
    double* hd  = (double*)(sm + OFF_HD);
    double* hdp = (double*)(sm + OFF_HDP);
    double* wd  = (double*)(sm + OFF_WD);
    double* cwd = (double*)(sm + OFF_CWD);
    float* Wc  = (float*)(sm + OFF_WC);
    float* Km  = (float*)(sm + OFF_KM);
    float* As  = (float*)(sm + OFF_AS);
    float* Hs  = (float*)(sm + OFF_HS);
    float* sa  = (float*)(sm + OFF_SA);
    float* sg  = (float*)(sm + OFF_SG);
    float* px  = (float*)(sm + OFF_PX);
    float* py  = (float*)(sm + OFF_PY);
    float* pz  = (float*)(sm + OFF_PZ);
    float* ens = (float*)(sm + OFF_EN);
    float* dgs = (float*)(sm + OFF_DG);
    float* rrs = (float*)(sm + OFF_RR);
    float* rf  = (float*)(sm + OFF_RF);
    float* rg  = (float*)(sm + OFF_RG);
    float* dinv= (float*)(sm + OFF_DI);
    int*   piv = (int*)(sm + OFF_PIV);
    int*   perm= (int*)(sm + OFF_PERM);

    const int mol = blockIdx.x;
    const int t = threadIdx.x;
    const int lane = t & 31;
    const int w = t >> 5;
    const float* Tm = T + (size_t)mol * (NAT * NE);
    const float* pm = positions + mol * NAT * 3;
    const int* eim = edge_index + mol * 2 * NE;
    const float q = total_charge[mol];

    // ---- per-atom small loads ----
    if (t < NAT) {
        px[t] = pm[3*t+0]; py[t] = pm[3*t+1]; pz[t] = pm[3*t+2];
        ens[t] = eneg[mol * NAT + t];
        float r = cov_radii[atomic_numbers[mol * NAT + t]];
        rrs[t] = r * r;
        const float* na = node_attrs + (size_t)(mol * NAT + t) * NUMEL;
        float best = na[0]; int bi = 0;
        #pragma unroll
        for (int j = 1; j < NUMEL; j++) { float v = na[j]; if (v > best) { best = v; bi = j; } }
        dgs[t] = hardness[bi] + 0.5641895835477563f / r;   // 1/sqrt(pi)/r
    }
    __syncthreads();

    // ---- A matrix (64x64, symmetric) ----
    for (int idx = t; idx < NAT * NAT; idx += 256) {
        int i = idx >> 6, j = idx & 63;
        float v;
        if (i == j) v = dgs[i];
        else {
            float dx = px[i]-px[j], dy = py[i]-py[j], dz = pz[i]-pz[j];
            float d = sqrtf(dx*dx + dy*dy + dz*dz);
            float arg = d * rsqrtf(2.0f * (rrs[i] + rrs[j]));
            v = erff(arg) / d;
        }
        As[idx] = v;
    }

    // ---- edges: sa[e] = sqrt(1/cut) (cancellation-free) ----
    for (int e = t; e < NE; e += 256) {
        int a0 = eim[e], a1 = eim[NE + e];
        float dx = px[a0]-px[a1], dy = py[a0]-py[a1], dz = pz[a0]-pz[a1];
        float ed = sqrtf(dx*dx + dy*dy + dz*dz);
        float th = 0.15707963267948966f * ed;   // pi*ed/(2*r_cut), r_cut=10
        float sh = sinf(0.5f * th);
        float ct = cosf(th);
        float dv = ct / (2.0f * sh * sh);       // 1/cut
        dv = fmaxf(dv, 1e-30f);
        sa[e] = sqrtf(dv);
    }
    __syncthreads();

    // ---- syrk tile geometry (13x5 = 65; 91 triangular tiles) ----
    const int g  = (lane >> 3);    // group within warp (4 tiles/warp/round)
    const int l8 = lane & 7;       // e-split lane

    // ---- chunk loop: build Wc, sg; accumulate H = W W^T and h = W sg ----
    for (int c = 0; c < 2; c++) {
        const int base = c * CH;
        // build Wc rows 0..63 = T*s (float4), row 64 = s
        for (int idx = t; idx < 64 * 64; idx += 256) {
            int a = idx >> 6, e = (idx & 63) * 4;
            float4 v  = *(const float4*)(Tm + a * NE + base + e);
            float4 s4 = *(const float4*)(sa + base + e);
            v.x *= s4.x; v.y *= s4.y; v.z *= s4.z; v.w *= s4.w;
            *(float4*)(Wc + a * WCP + e) = v;
        }
        if (t < 64) *(float4*)(Wc + 64 * WCP + 4*t) = *(const float4*)(sa + base + 4*t);
        __syncthreads();

        // sg[base+e] = -(sum_n Wc[n][e]*ens[n]) - sa*q   (one edge per thread)
        {
            float acc = 0.f;
            #pragma unroll 8
            for (int n = 0; n < NAT; n++) acc = fmaf(Wc[n * WCP + t], ens[n], acc);
            sg[base + t] = -acc - sa[base + t] * q;
        }
        __syncthreads();

        // syrk: 3 rounds x (8 warps x 4 groups) tiles
        for (int r = 0; r < 3; r++) {
            int p = r * 32 + w * 4 + g;
            bool act = (p < 91);
            int pp = act ? p : 0;
            int ti = (int)((sqrtf(8.0f * pp + 1.0f) - 1.0f) * 0.5f);
            while ((ti + 1) * (ti + 2) / 2 <= pp) ++ti;
            while (ti * (ti + 1) / 2 > pp) --ti;
            int tj = pp - ti * (ti + 1) / 2;
            const float* Wa = Wc + (ti * 5) * WCP;
            const float* Wb = Wc + (tj * 5) * WCP;
            float acc[25];
            #pragma unroll
            for (int m = 0; m < 25; m++) acc[m] = 0.f;
            for (int e = l8; e < CH; e += 8) {
                float ra[5], rb[5];
                #pragma unroll
                for (int i = 0; i < 5; i++) { ra[i] = Wa[i*WCP+e]; rb[i] = Wb[i*WCP+e]; }
                #pragma unroll
                for (int i = 0; i < 5; i++)
                    #pragma unroll
                    for (int j = 0; j < 5; j++)
                        acc[i*5+j] = fmaf(ra[i], rb[j], acc[i*5+j]);
            }
            // reduce over the 8 lanes of each group
            #pragma unroll
            for (int m = 0; m < 25; m++) {
                acc[m] += __shfl_down_sync(0xffffffffu, acc[m], 4);
                acc[m] += __shfl_down_sync(0xffffffffu, acc[m], 2);
                acc[m] += __shfl_down_sync(0xffffffffu, acc[m], 1);
            }
            if (act && l8 == 0) {
                #pragma unroll
                for (int i = 0; i < 5; i++)
                    #pragma unroll
                    for (int j = 0; j < 5; j++) {
                        int lo = (ti*5+i) * HP + (tj*5+j);
                        float v = acc[i*5+j];
                        if (c == 0) Hs[lo] = v; else Hs[lo] += v;
                        if (ti != tj) {
                            int up = (tj*5+j) * HP + (ti*5+i);
                            if (c == 0) Hs[up] = v; else Hs[up] += v;
                        }
                    }
            }
        }
        // h partials (fp64): 2 threads per row
        if (t < 130) {
            int row = t >> 1, part = t & 1;
            const float* Wr = Wc + row * WCP + part * 128;
            const float* sp = sg + base + part * 128;
            double a0=0, a1=0, a2=0, a3=0;
            for (int e = 0; e < 128; e += 4) {
                a0 += (double)Wr[e]   * (double)sp[e];
                a1 += (double)Wr[e+1] * (double)sp[e+1];
                a2 += (double)Wr[e+2] * (double)sp[e+2];
                a3 += (double)Wr[e+3] * (double)sp[e+3];
            }
            double tot = (a0 + a1) + (a2 + a3);
            hdp[t] = (c == 0) ? tot : hdp[t] + tot;
        }
        __syncthreads();
    }

    // ---- K = I + H*C (C = blockdiag(A,-1)); Km aliases Wc (now dead) ----
    if (t < NA) {
        double hv = hdp[2*t] + hdp[2*t+1];
        hd[t] = hv;
        Km[t * KP + 65] = (float)hv;                         // rhs column
        Km[t * KP + 64] = ((t == 64) ? 1.0f : 0.0f) - Hs[t * HP + 64];
    }
    for (int idx = t; idx < NA * 16; idx += 256) {
        int a = idx >> 4, c0 = (idx & 15) * 4;
        const float* Hr = Hs + a * HP;
        float4 acc = make_float4(0.f, 0.f, 0.f, 0.f);
        #pragma unroll 4
        for (int kq = 0; kq < 16; kq++) {
            float4 h4 = *(const float4*)(Hr + kq * 4);
            float4 a0 = *(const float4*)(As + (c0+0) * 64 + kq * 4);
            float4 a1 = *(const float4*)(As + (c0+1) * 64 + kq * 4);
            float4 a2 = *(const float4*)(As + (c0+2) * 64 + kq * 4);
            float4 a3 = *(const float4*)(As + (c0+3) * 64 + kq * 4);
            acc.x = fmaf(h4.x,a0.x,fmaf(h4.y,a0.y,fmaf(h4.z,a0.z,fmaf(h4.w,a0.w,acc.x))));
            acc.y = fmaf(h4.x,a1.x,fmaf(h4.y,a1.y,fmaf(h4.z,a1.z,fmaf(h4.w,a1.w,acc.y))));
            acc.z = fmaf(h4.x,a2.x,fmaf(h4.y,a2.y,fmaf(h4.z,a2.z,fmaf(h4.w,a2.w,acc.z))));
            acc.w = fmaf(h4.x,a3.x,fmaf(h4.y,a3.y,fmaf(h4.z,a3.z,fmaf(h4.w,a3.w,acc.w))));
        }
        Km[a * KP + c0 + 0] = acc.x + ((a == c0+0) ? 1.0f : 0.0f);
        Km[a * KP + c0 + 1] = acc.y + ((a == c0+1) ? 1.0f : 0.0f);
        Km[a * KP + c0 + 2] = acc.z + ((a == c0+2) ? 1.0f : 0.0f);
        Km[a * KP + c0 + 3] = acc.w + ((a == c0+3) ? 1.0f : 0.0f);
    }
    __syncthreads();

    // ---- LU with partial pivoting (3 barriers/iter, fused scale) ----
    for (int k = 0; k < NA; k++) {
        if (t < 32) {
            float bv = -1.f; int bi = k;
            for (int i = k + t; i < NA; i += 32) {
                float v = fabsf(Km[i * KP + k]);
                if (v > bv) { bv = v; bi = i; }
            }
            #pragma unroll
            for (int off = 16; off; off >>= 1) {
                float ov = __shfl_down_sync(0xffffffffu, bv, off);
                int   oi = __shfl_down_sync(0xffffffffu, bi, off);
                if (ov > bv) { bv = ov; bi = oi; }
            }
            if (t == 0) piv[k] = bi;
        }
        __syncthreads();
        int pv = piv[k];
        if (pv != k && t < 66) {
            float a = Km[k * KP + t], b = Km[pv * KP + t];
            Km[k * KP + t] = b; Km[pv * KP + t] = a;
        }
        __syncthreads();
        int i = k + 1 + (t >> 2);
        bool act = (i < NA);
        float old = act ? Km[i * KP + k] : 0.f;
        float pinv = 1.0f / Km[k * KP + k];
        __syncwarp();
        float mult = old * pinv;
        if (act) {
            if ((t & 3) == 0) Km[i * KP + k] = mult;
            for (int j = k + 1 + (t & 3); j <= 65; j += 4)
                Km[i * KP + j] = fmaf(-mult, Km[k * KP + j], Km[i * KP + j]);
        }
        __syncthreads();
    }

    // ---- dinv + perm (warp1) + back-substitution (warp0, syncwarp only) ----
    if (t == 32) {   // build composed permutation once
        for (int i = 0; i < NA; i++) perm[i] = i;
        for (int k = 0; k < NA; k++) {
            int pv = piv[k];
            if (pv != k) { int tmp = perm[k]; perm[k] = perm[pv]; perm[pv] = tmp; }
        }
    }
    if (t < 32) {
        for (int i = t; i < NA; i += 32) { dinv[i] = 1.0f / Km[i*KP+i]; rf[i] = Km[i*KP+65]; }
        __syncwarp();
        for (int k = NA - 1; k >= 0; k--) {
            float xk = rf[k] * dinv[k];
            __syncwarp();
            if (t == 0) rf[k] = xk;
            if (t < k) rf[t] = fmaf(-Km[t*KP+k], xk, rf[t]);
            int i2 = t + 32; if (i2 < k) rf[i2] = fmaf(-Km[i2*KP+k], xk, rf[i2]);
            __syncwarp();
        }
        for (int i = t; i < NA; i += 32) wd[i] = (double)rf[i];
    }
    __syncthreads();

    // ---- 2x fp64-residual iterative refinement ----
    for (int it = 0; it < 2; it++) {
        // cwd = C*wd
        for (int kk = w; kk < NAT; kk += 8) {
            const float* Ar = As + kk * 64;
            double acc = 0.0;
            for (int cc = lane; cc < NAT; cc += 32) acc += (double)Ar[cc] * wd[cc];
            #pragma unroll
            for (int off = 16; off; off >>= 1) acc += __shfl_down_sync(0xffffffffu, acc, off);
            if (lane == 0) cwd[kk] = acc;
        }
        if (t == 0) cwd[64] = -wd[64];
        __syncthreads();
        // rf = h - w - H*cwd
        for (int a = w; a < NA; a += 8) {
            const float* Hr = Hs + a * HP;
            double acc = 0.0;
            for (int k2 = lane; k2 < NA; k2 += 32) acc += (double)Hr[k2] * cwd[k2];
            #pragma unroll
            for (int off = 16; off; off >>= 1) acc += __shfl_down_sync(0xffffffffu, acc, off);
            if (lane == 0) rf[a] = (float)(hd[a] - wd[a] - acc);
        }
        __syncthreads();
        // permute + triangular solves, single warp
        if (t < 32) {
            for (int i = t; i < NA; i += 32) rg[i] = rf[perm[i]];
            __syncwarp();
            for (int k = 0; k < NA - 1; k++) {          // forward (unit L)
                float xk = rg[k];
                int i = k + 1 + t;  if (i < NA) rg[i] = fmaf(-Km[i*KP+k], xk, rg[i]);
                i = k + 33 + t;     if (i < NA) rg[i] = fmaf(-Km[i*KP+k], xk, rg[i]);
                __syncwarp();
            }
            for (int k = NA - 1; k >= 0; k--) {         // backward (U)
                float xk = rg[k] * dinv[k];
                __syncwarp();
                if (t == 0) rg[k] = xk;
                if (t < k) rg[t] = fmaf(-Km[t*KP+k], xk, rg[t]);
                int i2 = t + 32; if (i2 < k) rg[i2] = fmaf(-Km[i2*KP+k], xk, rg[i2]);
                __syncwarp();
            }
            for (int i = t; i < NA; i += 32) wd[i] += (double)rg[i];
        }
        __syncthreads();
    }

    // ---- output ----
    if (t < NAT) out[mol * NAT + t] = (float)wd[t];
}

extern "C" void kernel_launch(void* const* d_in, const int* in_sizes, int n_in,
                              void* d_out, int out_size)
{
    const float* positions      = (const float*)d_in[0];
    const float* T              = (const float*)d_in[1];
    const float* eneg           = (const float*)d_in[2];
    const float* node_attrs     = (const float*)d_in[3];
    const float* total_charge   = (const float*)d_in[4];
    /* d_in[5] = p (unused) */
    const float* hardness       = (const float*)d_in[6];
    const float* cov_radii      = (const float*)d_in[7];
    const int*   atomic_numbers = (const int*)d_in[8];
    const int*   edge_index     = (const int*)d_in[9];
    float* out = (float*)d_out;

    int B = in_sizes[4];
    cudaFuncSetAttribute(cheq_kernel, cudaFuncAttributeMaxDynamicSharedMemorySize, SMEM_BYTES);
    cheq_kernel<<<B, 256, SMEM_BYTES>>>(positions, T, eneg, node_attrs, total_charge,
                                        hardness, cov_radii, atomic_numbers, edge_index, out);
}

// round 5
// speedup vs baseline: 1.6729x; 1.0710x over previous
#include <cuda_runtime.h>
#include <math.h>

typedef unsigned long long ull;

constexpr int NAT = 64;
constexpr int NE  = 512;
constexpr int NA  = 65;
constexpr int NUMEL = 10;
constexpr int CH  = 256;    // chunk width (edges)
constexpr int WCP = 260;    // Wc pitch (floats)
constexpr int HP  = 68;     // Hs pitch
constexpr int KP  = 67;     // Km pitch

// ---- shared memory byte offsets ----
constexpr int OFF_HD  = 0;                      // double hd[65]
constexpr int OFF_WD  = 528;                    // double wd[65]
constexpr int OFF_CWD = 1056;                   // double cwd[65]
constexpr int OFF_WC  = 1584;                   // float Wc[65][260]
constexpr int OFF_KM  = OFF_WC;                 // float Km[65][67] (aliases Wc)
constexpr int OFF_AS  = OFF_WC + 65*WCP*4;      // float As[64][64]
constexpr int OFF_HS  = OFF_AS + 64*64*4;       // float Hs[65][68]
constexpr int OFF_SA  = OFF_HS + 65*HP*4;       // float sa[512]
constexpr int OFF_SG  = OFF_SA + 2048;          // float sg[512]
constexpr int OFF_PX  = OFF_SG + 2048;
constexpr int OFF_PY  = OFF_PX + 256;
constexpr int OFF_PZ  = OFF_PY + 256;
constexpr int OFF_EN  = OFF_PZ + 256;
constexpr int OFF_DG  = OFF_EN + 256;
constexpr int OFF_RR  = OFF_DG + 256;
constexpr int OFF_RF  = OFF_RR + 256;           // float rf[68]
constexpr int OFF_RG  = OFF_RF + 272;           // float rg[68]
constexpr int OFF_DI  = OFF_RG + 272;           // float dinv[68]
constexpr int OFF_RP  = OFF_DI + 272;           // int rowperm[68]
constexpr int OFF_SC  = OFF_RP + 272;           // int scal[4]
constexpr int SMEM_BYTES = OFF_SC + 16;         // ~110 KB -> 2 CTAs/SM

__device__ __forceinline__ ull ffma2(ull a, ull b, ull c) {
    ull d;
    asm("fma.rn.f32x2 %0, %1, %2, %3;" : "=l"(d) : "l"(a), "l"(b), "l"(c));
    return d;
}
__device__ __forceinline__ ull fadd2(ull a, ull b) {
    ull d;
    asm("add.rn.f32x2 %0, %1, %2;" : "=l"(d) : "l"(a), "l"(b));
    return d;
}
__device__ __forceinline__ float2 unpack2(ull v) {
    float2 f;
    asm("mov.b64 {%0,%1}, %2;" : "=f"(f.x), "=f"(f.y) : "l"(v));
    return f;
}

__global__ __launch_bounds__(256, 2)
void cheq_kernel(const float* __restrict__ positions,
                 const float* __restrict__ T,
                 const float* __restrict__ eneg,
                 const float* __restrict__ node_attrs,
                 const float* __restrict__ total_charge,
                 const float* __restrict__ hardness,
                 const float* __restrict__ cov_radii,
                 const int*   __restrict__ atomic_numbers,
                 const int*   __restrict__ edge_index,
                 float* __restrict__ out)
{
    extern __shared__ __align__(16) unsigned char sm[];
    double* hd  = (double*)(sm + OFF_HD);
    double* wd  = (double*)(sm + OFF_WD);
    double* cwd = (double*)(sm + OFF_CWD);
    float* Wc  = (float*)(sm + OFF_WC);
    float* Km  = (float*)(sm + OFF_KM);
    float* As  = (float*)(sm + OFF_AS);
    float* Hs  = (float*)(sm + OFF_HS);
    float* sa  = (float*)(sm + OFF_SA);
    float* sg  = (float*)(sm + OFF_SG);
    float* px  = (float*)(sm + OFF_PX);
    float* py  = (float*)(sm + OFF_PY);
    float* pz  = (float*)(sm + OFF_PZ);
    float* ens = (float*)(sm + OFF_EN);
    float* dgs = (float*)(sm + OFF_DG);
    float* rrs = (float*)(sm + OFF_RR);
    float* rf  = (float*)(sm + OFF_RF);
    float* rg  = (float*)(sm + OFF_RG);
    float* dinv= (float*)(sm + OFF_DI);
    int* rowperm = (int*)(sm + OFF_RP);
    int* scal    = (int*)(sm + OFF_SC);

    const int mol = blockIdx.x;
    const int t = threadIdx.x;
    const int lane = t & 31;
    const int w = t >> 5;
    const float* Tm = T + (size_t)mol * (NAT * NE);
    const float* pm = positions + mol * NAT * 3;
    const int* eim = edge_index + mol * 2 * NE;
    const float q = total_charge[mol];

    // ---- per-atom small loads ----
    if (t < NAT) {
        px[t] = pm[3*t+0]; py[t] = pm[3*t+1]; pz[t] = pm[3*t+2];
        ens[t] = eneg[mol * NAT + t];
        float r = cov_radii[atomic_numbers[mol * NAT + t]];
        rrs[t] = r * r;
        const float* na = node_attrs + (size_t)(mol * NAT + t) * NUMEL;
        float best = na[0]; int bi = 0;
        #pragma unroll
        for (int j = 1; j < NUMEL; j++) { float v = na[j]; if (v > best) { best = v; bi = j; } }
        dgs[t] = hardness[bi] + 0.5641895835477563f / r;
    }
    if (t < NA) rowperm[t] = t;
    __syncthreads();

    // ---- A matrix (64x64, symmetric) ----
    for (int idx = t; idx < NAT * NAT; idx += 256) {
        int i = idx >> 6, j = idx & 63;
        float v;
        if (i == j) v = dgs[i];
        else {
            float dx = px[i]-px[j], dy = py[i]-py[j], dz = pz[i]-pz[j];
            float d = sqrtf(dx*dx + dy*dy + dz*dz);
            float arg = d * rsqrtf(2.0f * (rrs[i] + rrs[j]));
            v = erff(arg) / d;
        }
        As[idx] = v;
    }

    // ---- edges: sa[e] = sqrt(1/cut), cancellation-free ----
    for (int e = t; e < NE; e += 256) {
        int a0 = eim[e], a1 = eim[NE + e];
        float dx = px[a0]-px[a1], dy = py[a0]-py[a1], dz = pz[a0]-pz[a1];
        float ed = sqrtf(dx*dx + dy*dy + dz*dz);
        float th = 0.15707963267948966f * ed;
        float sh = sinf(0.5f * th);
        float ct = cosf(th);
        float dv = ct / (2.0f * sh * sh);
        dv = fmaxf(dv, 1e-30f);
        sa[e] = sqrtf(dv);
    }
    __syncthreads();

    // ---- syrk tile geometry (91 triangular 5x5 tiles over 13 strips) ----
    const int g  = (lane >> 3);
    const int l8 = lane & 7;
    int tiR[3], tjR[3]; bool actR[3];
    #pragma unroll
    for (int r = 0; r < 3; r++) {
        int p = r * 32 + w * 4 + g;
        actR[r] = (p < 91);
        int pp = actR[r] ? p : 0;
        int ti = (int)((sqrtf(8.0f * pp + 1.0f) - 1.0f) * 0.5f);
        while ((ti + 1) * (ti + 2) / 2 <= pp) ++ti;
        while (ti * (ti + 1) / 2 > pp) --ti;
        tiR[r] = ti; tjR[r] = pp - ti * (ti + 1) / 2;
    }

    // ---- chunk loop ----
    for (int c = 0; c < 2; c++) {
        const int base = c * CH;
        // Wc rows 0..63 = T*s (float4), row 64 = s
        for (int idx = t; idx < 64 * 64; idx += 256) {
            int a = idx >> 6, e = (idx & 63) * 4;
            float4 v  = *(const float4*)(Tm + a * NE + base + e);
            float4 s4 = *(const float4*)(sa + base + e);
            v.x *= s4.x; v.y *= s4.y; v.z *= s4.z; v.w *= s4.w;
            *(float4*)(Wc + a * WCP + e) = v;
        }
        if (t < 64) *(float4*)(Wc + 64 * WCP + 4*t) = *(const float4*)(sa + base + 4*t);
        __syncthreads();

        // sg[base+t] = -(col_t of Wc . ens) - sa*q
        {
            float acc = 0.f;
            #pragma unroll 8
            for (int n = 0; n < NAT; n++) acc = fmaf(Wc[n * WCP + t], ens[n], acc);
            sg[base + t] = -acc - sa[base + t] * q;
        }
        __syncthreads();

        // syrk: packed f32x2 FMAs, LDS.64 loads
        #pragma unroll
        for (int r = 0; r < 3; r++) {
            const float* Wa = Wc + (tiR[r] * 5) * WCP;
            const float* Wb = Wc + (tjR[r] * 5) * WCP;
            ull acc[25];
            #pragma unroll
            for (int m = 0; m < 25; m++) acc[m] = 0ull;
            for (int e = 4 * l8; e < CH; e += 32) {
                ull a0[5], a1[5];
                #pragma unroll
                for (int i = 0; i < 5; i++) {
                    a0[i] = *(const ull*)(Wa + i * WCP + e);
                    a1[i] = *(const ull*)(Wa + i * WCP + e + 2);
                }
                #pragma unroll
                for (int j = 0; j < 5; j++) {
                    ull b0 = *(const ull*)(Wb + j * WCP + e);
                    ull b1 = *(const ull*)(Wb + j * WCP + e + 2);
                    #pragma unroll
                    for (int i = 0; i < 5; i++) {
                        acc[i*5+j] = ffma2(a0[i], b0, acc[i*5+j]);
                        acc[i*5+j] = ffma2(a1[i], b1, acc[i*5+j]);
                    }
                }
            }
            #pragma unroll
            for (int m = 0; m < 25; m++) {
                acc[m] = fadd2(acc[m], __shfl_down_sync(0xffffffffu, acc[m], 4));
                acc[m] = fadd2(acc[m], __shfl_down_sync(0xffffffffu, acc[m], 2));
                acc[m] = fadd2(acc[m], __shfl_down_sync(0xffffffffu, acc[m], 1));
            }
            if (actR[r] && l8 == 0) {
                int ti = tiR[r], tj = tjR[r];
                #pragma unroll
                for (int i = 0; i < 5; i++)
                    #pragma unroll
                    for (int j = 0; j < 5; j++) {
                        float2 f = unpack2(acc[i*5+j]);
                        float v = f.x + f.y;
                        int lo = (ti*5+i) * HP + (tj*5+j);
                        if (c == 0) Hs[lo] = v; else Hs[lo] += v;
                        if (ti != tj) {
                            int up = (tj*5+j) * HP + (ti*5+i);
                            if (c == 0) Hs[up] = v; else Hs[up] += v;
                        }
                    }
            }
        }

        // h = W*sg in fp64 (DFMA), warp-per-row, lane-strided
        for (int a = w; a < NA; a += 8) {
            const float* Wr = Wc + a * WCP;
            const float* sp = sg + base;
            double acc = 0.0;
            #pragma unroll
            for (int e = 0; e < CH / 32; e++) {
                int ei = lane + e * 32;
                acc = fma((double)Wr[ei], (double)sp[ei], acc);
            }
            #pragma unroll
            for (int off = 16; off; off >>= 1)
                acc += __shfl_down_sync(0xffffffffu, acc, off);
            if (lane == 0) { if (c == 0) hd[a] = acc; else hd[a] += acc; }
        }
        __syncthreads();
    }

    // ---- K = I + H*C; Km aliases Wc (dead) ----
    if (t < NA) {
        Km[t * KP + 65] = (float)hd[t];
        Km[t * KP + 64] = ((t == 64) ? 1.0f : 0.0f) - Hs[t * HP + 64];
    }
    for (int idx = t; idx < NA * 16; idx += 256) {
        int a = idx >> 4, c0 = (idx & 15) * 4;
        const float* Hr = Hs + a * HP;
        float4 acc = make_float4(0.f, 0.f, 0.f, 0.f);
        #pragma unroll 4
        for (int kq = 0; kq < 16; kq++) {
            float4 h4 = *(const float4*)(Hr + kq * 4);
            float4 a0 = *(const float4*)(As + (c0+0) * 64 + kq * 4);
            float4 a1 = *(const float4*)(As + (c0+1) * 64 + kq * 4);
            float4 a2 = *(const float4*)(As + (c0+2) * 64 + kq * 4);
            float4 a3 = *(const float4*)(As + (c0+3) * 64 + kq * 4);
            acc.x = fmaf(h4.x,a0.x,fmaf(h4.y,a0.y,fmaf(h4.z,a0.z,fmaf(h4.w,a0.w,acc.x))));
            acc.y = fmaf(h4.x,a1.x,fmaf(h4.y,a1.y,fmaf(h4.z,a1.z,fmaf(h4.w,a1.w,acc.y))));
            acc.z = fmaf(h4.x,a2.x,fmaf(h4.y,a2.y,fmaf(h4.z,a2.z,fmaf(h4.w,a2.w,acc.z))));
            acc.w = fmaf(h4.x,a3.x,fmaf(h4.y,a3.y,fmaf(h4.z,a3.z,fmaf(h4.w,a3.w,acc.w))));
        }
        Km[a * KP + c0 + 0] = acc.x + ((a == c0+0) ? 1.0f : 0.0f);
        Km[a * KP + c0 + 1] = acc.y + ((a == c0+1) ? 1.0f : 0.0f);
        Km[a * KP + c0 + 2] = acc.z + ((a == c0+2) ? 1.0f : 0.0f);
        Km[a * KP + c0 + 3] = acc.w + ((a == c0+3) ? 1.0f : 0.0f);
    }
    __syncthreads();

    // ---- LU, implicit pivoting via rowperm: 2 barriers/iter ----
    for (int k = 0; k < NA; k++) {
        if (t < 32) {
            float bv = -1.f; int bi = k;
            for (int i = k + t; i < NA; i += 32) {
                int ph = rowperm[i];
                float v = fabsf(Km[ph * KP + k]);
                if (v > bv) { bv = v; bi = i; }
            }
            #pragma unroll
            for (int off = 16; off; off >>= 1) {
                float ov = __shfl_down_sync(0xffffffffu, bv, off);
                int   oi = __shfl_down_sync(0xffffffffu, bi, off);
                if (ov > bv) { bv = ov; bi = oi; }
            }
            if (t == 0) {
                int pk = rowperm[bi];
                if (bi != k) { rowperm[bi] = rowperm[k]; rowperm[k] = pk; }
                dinv[k] = 1.0f / Km[pk * KP + k];
                scal[0] = pk;
            }
        }
        __syncthreads();
        int pk = scal[0];
        float pinv = dinv[k];
        int lr = k + 1 + (t >> 2);
        if (lr < NA) {
            int ph = rowperm[lr];
            float* crow = Km + ph * KP;
            const float* prow = Km + pk * KP;
            float m = crow[k] * pinv;
            if ((t & 3) == 0) crow[k] = m;
            for (int j = k + 1 + (t & 3); j <= 65; j += 4)
                crow[j] = fmaf(-m, prow[j], crow[j]);
        }
        __syncthreads();
    }

    // ---- back-substitution (warp 0); thread 0 also carries row 64 ----
    if (t < 32) {
        int p0 = rowperm[t];
        int p1 = rowperm[t + 32];          // t+32 in 32..63, always < NA
        rf[t] = Km[p0 * KP + 65];
        rf[t + 32] = Km[p1 * KP + 65];
        if (t == 0) rf[64] = Km[rowperm[64] * KP + 65];
        __syncwarp();
        for (int k = NA - 1; k >= 0; k--) {
            float xk = rf[k] * dinv[k];
            __syncwarp();
            if (t == 0) rf[k] = xk;
            if (t < k) rf[t] = fmaf(-Km[p0 * KP + k], xk, rf[t]);
            int i2 = t + 32; if (i2 < k) rf[i2] = fmaf(-Km[p1 * KP + k], xk, rf[i2]);
            __syncwarp();
        }
        for (int i = t; i < NA; i += 32) wd[i] = (double)rf[i];
    }
    __syncthreads();

    // ---- 1x fp64-residual iterative refinement (65x65 only) ----
    {
        for (int kk = w; kk < NAT; kk += 8) {
            const float* Ar = As + kk * 64;
            double acc = 0.0;
            for (int cc = lane; cc < NAT; cc += 32) acc += (double)Ar[cc] * wd[cc];
            #pragma unroll
            for (int off = 16; off; off >>= 1) acc += __shfl_down_sync(0xffffffffu, acc, off);
            if (lane == 0) cwd[kk] = acc;
        }
        if (t == 0) cwd[64] = -wd[64];
        __syncthreads();
        for (int a = w; a < NA; a += 8) {
            const float* Hr = Hs + a * HP;
            double acc = 0.0;
            for (int k2 = lane; k2 < NA; k2 += 32) acc += (double)Hr[k2] * cwd[k2];
            #pragma unroll
            for (int off = 16; off; off >>= 1) acc += __shfl_down_sync(0xffffffffu, acc, off);
            if (lane == 0) rf[a] = (float)(hd[a] - wd[a] - acc);
        }
        __syncthreads();
        if (t < 32) {
            int p0 = rowperm[t];
            int p1 = rowperm[t + 32];
            rg[t] = rf[p0];
            rg[t + 32] = rf[p1];
            if (t == 0) rg[64] = rf[rowperm[64]];
            __syncwarp();
            for (int k = 0; k < NA - 1; k++) {          // forward (unit L), rows k+1..k+64
                float xk = rg[k];
                int i = k + 1 + t;
                if (i < NA) rg[i] = fmaf(-Km[rowperm[i] * KP + k], xk, rg[i]);
                i = k + 33 + t;
                if (i < NA) rg[i] = fmaf(-Km[rowperm[i] * KP + k], xk, rg[i]);
                __syncwarp();
            }
            for (int k = NA - 1; k >= 0; k--) {         // backward (U)
                float xk = rg[k] * dinv[k];
                __syncwarp();
                if (t == 0) rg[k] = xk;
                if (t < k) rg[t] = fmaf(-Km[p0 * KP + k], xk, rg[t]);
                int i2 = t + 32; if (i2 < k) rg[i2] = fmaf(-Km[p1 * KP + k], xk, rg[i2]);
                __syncwarp();
            }
            for (int i = t; i < NA; i += 32) wd[i] += (double)rg[i];
        }
        __syncthreads();
    }

    // ---- output ----
    if (t < NAT) out[mol * NAT + t] = (float)wd[t];
}

extern "C" void kernel_launch(void* const* d_in, const int* in_sizes, int n_in,
                              void* d_out, int out_size)
{
    const float* positions      = (const float*)d_in[0];
    const float* T              = (const float*)d_in[1];
    const float* eneg           = (const float*)d_in[2];
    const float* node_attrs     = (const float*)d_in[3];
    const float* total_charge   = (const float*)d_in[4];
    const float* hardness       = (const float*)d_in[6];
    const float* cov_radii      = (const float*)d_in[7];
    const int*   atomic_numbers = (const int*)d_in[8];
    const int*   edge_index     = (const int*)d_in[9];
    float* out = (float*)d_out;

    int B = in_sizes[4];
    cudaFuncSetAttribute(cheq_kernel, cudaFuncAttributeMaxDynamicSharedMemorySize, SMEM_BYTES);
    cheq_kernel<<<B, 256, SMEM_BYTES>>>(positions, T, eneg, node_attrs, total_charge,
                                        hardness, cov_radii, atomic_numbers, edge_index, out);
}

// round 6
// speedup vs baseline: 1.9022x; 1.1371x over previous
#include <cuda_runtime.h>
#include <math.h>

typedef unsigned long long ull;

constexpr int NAT = 64;
constexpr int NE  = 512;
constexpr int NA  = 65;
constexpr int NUMEL = 10;
constexpr int CH  = 256;    // chunk width (edges)
constexpr int WCP = 260;    // Wc pitch (floats)
constexpr int HP  = 68;     // Hs pitch
constexpr int KP  = 67;     // Km pitch
constexpr int NTH = 384;    // threads per CTA (12 warps)

// ---- shared memory byte offsets ----
constexpr int OFF_HD  = 0;                       // double hd[65]
constexpr int OFF_WD  = 528;                     // double wd[65]
constexpr int OFF_CWD = 1056;                    // double cwd[65]
constexpr int OFF_WC  = 1584;                    // float Wc[65][260]
constexpr int OFF_KM  = OFF_WC;                  // float Km[65][67] (aliases Wc)
constexpr int OFF_AS  = OFF_WC + 65*WCP*4;       // 69184: float As[64][64]
constexpr int OFF_HS  = OFF_AS + 64*64*4;        // 85568: float Hs[65][68]
constexpr int OFF_SA  = OFF_HS + 65*HP*4;        // 103248: float sa[512]
constexpr int OFF_SG  = OFF_SA + 2048;           // float sg[512]
constexpr int OFF_PX  = OFF_SG + 2048;
constexpr int OFF_PY  = OFF_PX + 256;
constexpr int OFF_PZ  = OFF_PY + 256;
constexpr int OFF_EN  = OFF_PZ + 256;
constexpr int OFF_DG  = OFF_EN + 256;
constexpr int OFF_RR  = OFF_DG + 256;
constexpr int OFF_RF  = OFF_RR + 256;            // float rf[68]
constexpr int OFF_RG  = OFF_RF + 272;            // float rg[68]
constexpr int OFF_DI  = OFF_RG + 272;            // float dinv[68]
constexpr int OFF_PH  = OFF_DI + 272;            // int pivhist[68]
constexpr int OFF_PM  = OFF_PH + 272;            // uint pmax[68]
constexpr int SMEM_BYTES = OFF_PM + 272;         // 110240 B (~107.7 KB) -> 2 CTAs/SM

__device__ __forceinline__ ull ffma2(ull a, ull b, ull c) {
    ull d;
    asm("fma.rn.f32x2 %0, %1, %2, %3;" : "=l"(d) : "l"(a), "l"(b), "l"(c));
    return d;
}
__device__ __forceinline__ ull fadd2(ull a, ull b) {
    ull d;
    asm("add.rn.f32x2 %0, %1, %2;" : "=l"(d) : "l"(a), "l"(b));
    return d;
}
__device__ __forceinline__ float2 unpack2(ull v) {
    float2 f;
    asm("mov.b64 {%0,%1}, %2;" : "=f"(f.x), "=f"(f.y) : "l"(v));
    return f;
}
// pack |v| and row into a monotone uint key (top 25 bits of |v|, row in low 7)
__device__ __forceinline__ unsigned int pivkey(float v, int row) {
    return (__float_as_uint(fabsf(v)) & 0xFFFFFF80u) | (unsigned int)row;
}

__global__ __launch_bounds__(NTH, 2)
void cheq_kernel(const float* __restrict__ positions,
                 const float* __restrict__ T,
                 const float* __restrict__ eneg,
                 const float* __restrict__ node_attrs,
                 const float* __restrict__ total_charge,
                 const float* __restrict__ hardness,
                 const float* __restrict__ cov_radii,
                 const int*   __restrict__ atomic_numbers,
                 const int*   __restrict__ edge_index,
                 float* __restrict__ out)
{
    extern __shared__ __align__(16) unsigned char sm[];
    double* hd  = (double*)(sm + OFF_HD);
    double* wd  = (double*)(sm + OFF_WD);
    double* cwd = (double*)(sm + OFF_CWD);
    float* Wc  = (float*)(sm + OFF_WC);
    float* Km  = (float*)(sm + OFF_KM);
    float* As  = (float*)(sm + OFF_AS);
    float* Hs  = (float*)(sm + OFF_HS);
    float* sa  = (float*)(sm + OFF_SA);
    float* sg  = (float*)(sm + OFF_SG);
    float* px  = (float*)(sm + OFF_PX);
    float* py  = (float*)(sm + OFF_PY);
    float* pz  = (float*)(sm + OFF_PZ);
    float* ens = (float*)(sm + OFF_EN);
    float* dgs = (float*)(sm + OFF_DG);
    float* rrs = (float*)(sm + OFF_RR);
    float* rf  = (float*)(sm + OFF_RF);
    float* rg  = (float*)(sm + OFF_RG);
    float* dinv= (float*)(sm + OFF_DI);
    int*   pivhist = (int*)(sm + OFF_PH);
    unsigned int* pmax = (unsigned int*)(sm + OFF_PM);

    const int mol = blockIdx.x;
    const int t = threadIdx.x;
    const int lane = t & 31;
    const int w = t >> 5;
    const float* Tm = T + (size_t)mol * (NAT * NE);
    const float* pm = positions + mol * NAT * 3;
    const int* eim = edge_index + mol * 2 * NE;
    const float q = total_charge[mol];

    // ---- per-atom small loads + pmax init ----
    if (t < NAT) {
        px[t] = pm[3*t+0]; py[t] = pm[3*t+1]; pz[t] = pm[3*t+2];
        ens[t] = eneg[mol * NAT + t];
        float r = cov_radii[atomic_numbers[mol * NAT + t]];
        rrs[t] = r * r;
        const float* na = node_attrs + (size_t)(mol * NAT + t) * NUMEL;
        float best = na[0]; int bi = 0;
        #pragma unroll
        for (int j = 1; j < NUMEL; j++) { float v = na[j]; if (v > best) { best = v; bi = j; } }
        dgs[t] = hardness[bi] + 0.5641895835477563f / r;
    }
    if (t < NA + 1) pmax[t] = 0u;
    __syncthreads();

    // ---- A matrix (64x64, symmetric) ----
    for (int idx = t; idx < NAT * NAT; idx += NTH) {
        int i = idx >> 6, j = idx & 63;
        float v;
        if (i == j) v = dgs[i];
        else {
            float dx = px[i]-px[j], dy = py[i]-py[j], dz = pz[i]-pz[j];
            float d = sqrtf(dx*dx + dy*dy + dz*dz);
            float arg = d * rsqrtf(2.0f * (rrs[i] + rrs[j]));
            v = erff(arg) / d;
        }
        As[idx] = v;
    }

    // ---- edges: sa[e] = sqrt(1/cut), cancellation-free ----
    for (int e = t; e < NE; e += NTH) {
        int a0 = eim[e], a1 = eim[NE + e];
        float dx = px[a0]-px[a1], dy = py[a0]-py[a1], dz = pz[a0]-pz[a1];
        float ed = sqrtf(dx*dx + dy*dy + dz*dz);
        float th = 0.15707963267948966f * ed;
        float sh = sinf(0.5f * th);
        float ct = cosf(th);
        float dv = ct / (2.0f * sh * sh);
        dv = fmaxf(dv, 1e-30f);
        sa[e] = sqrtf(dv);
    }
    __syncthreads();

    // ---- syrk tile geometry (91 triangular 5x5 tiles; 12 warps x 4 groups x 2 rounds) ----
    const int g  = (lane >> 3);
    const int l8 = lane & 7;
    int tiR[2], tjR[2]; bool actR[2];
    #pragma unroll
    for (int r = 0; r < 2; r++) {
        int p = r * 48 + w * 4 + g;
        actR[r] = (p < 91);
        int pp = actR[r] ? p : 0;
        int ti = (int)((sqrtf(8.0f * pp + 1.0f) - 1.0f) * 0.5f);
        while ((ti + 1) * (ti + 2) / 2 <= pp) ++ti;
        while (ti * (ti + 1) / 2 > pp) --ti;
        tiR[r] = ti; tjR[r] = pp - ti * (ti + 1) / 2;
    }

    // ---- chunk loop ----
    for (int c = 0; c < 2; c++) {
        const int base = c * CH;
        // Wc rows 0..63 = T*s (float4), row 64 = s
        for (int idx = t; idx < 64 * 64; idx += NTH) {
            int a = idx >> 6, e = (idx & 63) * 4;
            float4 v  = *(const float4*)(Tm + a * NE + base + e);
            float4 s4 = *(const float4*)(sa + base + e);
            v.x *= s4.x; v.y *= s4.y; v.z *= s4.z; v.w *= s4.w;
            *(float4*)(Wc + a * WCP + e) = v;
        }
        if (t < 64) *(float4*)(Wc + 64 * WCP + 4*t) = *(const float4*)(sa + base + 4*t);
        __syncthreads();

        // sg (threads 0..255, one edge each) — syrk below doesn't need sg
        if (t < CH) {
            float acc = 0.f;
            #pragma unroll 8
            for (int n = 0; n < NAT; n++) acc = fmaf(Wc[n * WCP + t], ens[n], acc);
            sg[base + t] = -acc - sa[base + t] * q;
        }

        // syrk: packed f32x2 FMAs, LDS.64 loads
        #pragma unroll
        for (int r = 0; r < 2; r++) {
            const float* Wa = Wc + (tiR[r] * 5) * WCP;
            const float* Wb = Wc + (tjR[r] * 5) * WCP;
            ull acc[25];
            #pragma unroll
            for (int m = 0; m < 25; m++) acc[m] = 0ull;
            for (int e = 4 * l8; e < CH; e += 32) {
                ull a0[5], a1[5];
                #pragma unroll
                for (int i = 0; i < 5; i++) {
                    a0[i] = *(const ull*)(Wa + i * WCP + e);
                    a1[i] = *(const ull*)(Wa + i * WCP + e + 2);
                }
                #pragma unroll
                for (int j = 0; j < 5; j++) {
                    ull b0 = *(const ull*)(Wb + j * WCP + e);
                    ull b1 = *(const ull*)(Wb + j * WCP + e + 2);
                    #pragma unroll
                    for (int i = 0; i < 5; i++) {
                        acc[i*5+j] = ffma2(a0[i], b0, acc[i*5+j]);
                        acc[i*5+j] = ffma2(a1[i], b1, acc[i*5+j]);
                    }
                }
            }
            #pragma unroll
            for (int m = 0; m < 25; m++) {
                acc[m] = fadd2(acc[m], __shfl_down_sync(0xffffffffu, acc[m], 4));
                acc[m] = fadd2(acc[m], __shfl_down_sync(0xffffffffu, acc[m], 2));
                acc[m] = fadd2(acc[m], __shfl_down_sync(0xffffffffu, acc[m], 1));
            }
            if (actR[r] && l8 == 0) {
                int ti = tiR[r], tj = tjR[r];
                #pragma unroll
                for (int i = 0; i < 5; i++)
                    #pragma unroll
                    for (int j = 0; j < 5; j++) {
                        float2 f = unpack2(acc[i*5+j]);
                        float v = f.x + f.y;
                        int lo = (ti*5+i) * HP + (tj*5+j);
                        if (c == 0) Hs[lo] = v; else Hs[lo] += v;
                        if (ti != tj) {
                            int up = (tj*5+j) * HP + (ti*5+i);
                            if (c == 0) Hs[up] = v; else Hs[up] += v;
                        }
                    }
            }
        }
        __syncthreads();   // sg + syrk done; h reads sg below

        // h = W*sg in fp64 (DFMA), warp-per-row, lane-strided
        for (int a = w; a < NA; a += 12) {
            const float* Wr = Wc + a * WCP;
            const float* sp = sg + base;
            double acc = 0.0;
            #pragma unroll
            for (int e = 0; e < CH / 32; e++) {
                int ei = lane + e * 32;
                acc = fma((double)Wr[ei], (double)sp[ei], acc);
            }
            #pragma unroll
            for (int off = 16; off; off >>= 1)
                acc += __shfl_down_sync(0xffffffffu, acc, off);
            if (lane == 0) { if (c == 0) hd[a] = acc; else hd[a] += acc; }
        }
        __syncthreads();   // Wc rebuilt next chunk
    }

    // ---- K = I + H*C; Km aliases Wc (dead). Seed pmax[0] during build. ----
    if (t < NA) {
        Km[t * KP + 65] = (float)hd[t];
        Km[t * KP + 64] = ((t == 64) ? 1.0f : 0.0f) - Hs[t * HP + 64];
    }
    for (int idx = t; idx < NA * 16; idx += NTH) {
        int a = idx >> 4, c0 = (idx & 15) * 4;
        const float* Hr = Hs + a * HP;
        float4 acc = make_float4(0.f, 0.f, 0.f, 0.f);
        #pragma unroll 4
        for (int kq = 0; kq < 16; kq++) {
            float4 h4 = *(const float4*)(Hr + kq * 4);
            float4 a0 = *(const float4*)(As + (c0+0) * 64 + kq * 4);
            float4 a1 = *(const float4*)(As + (c0+1) * 64 + kq * 4);
            float4 a2 = *(const float4*)(As + (c0+2) * 64 + kq * 4);
            float4 a3 = *(const float4*)(As + (c0+3) * 64 + kq * 4);
            acc.x = fmaf(h4.x,a0.x,fmaf(h4.y,a0.y,fmaf(h4.z,a0.z,fmaf(h4.w,a0.w,acc.x))));
            acc.y = fmaf(h4.x,a1.x,fmaf(h4.y,a1.y,fmaf(h4.z,a1.z,fmaf(h4.w,a1.w,acc.y))));
            acc.z = fmaf(h4.x,a2.x,fmaf(h4.y,a2.y,fmaf(h4.z,a2.z,fmaf(h4.w,a2.w,acc.z))));
            acc.w = fmaf(h4.x,a3.x,fmaf(h4.y,a3.y,fmaf(h4.z,a3.z,fmaf(h4.w,a3.w,acc.w))));
        }
        float v0 = acc.x + ((a == c0+0) ? 1.0f : 0.0f);
        Km[a * KP + c0 + 0] = v0;
        Km[a * KP + c0 + 1] = acc.y + ((a == c0+1) ? 1.0f : 0.0f);
        Km[a * KP + c0 + 2] = acc.z + ((a == c0+2) ? 1.0f : 0.0f);
        Km[a * KP + c0 + 3] = acc.w + ((a == c0+3) ? 1.0f : 0.0f);
        if (c0 == 0) atomicMax(&pmax[0], pivkey(v0, a));   // seed pivot for step 0
    }
    __syncthreads();

    // ---- Gauss-Jordan with partial pivoting: 1 barrier per step ----
    // Teams of 5 threads own fixed physical rows; pivot for step k+1 is
    // selected via atomicMax on packed |value|+row during step k's update.
    {
        const int team = t / 5;                 // 0..64 for t<325
        const int sub  = t - team * 5;
        const bool tval = (t < 325);
        bool mypivoted = false;
        float* myrow = Km + team * KP;
        for (int k = 0; k < NA; k++) {
            int pk = (int)(pmax[k] & 0x7Fu);
            const float* prow = Km + pk * KP;
            float pinv = 1.0f / prow[k];
            if (t == 0) { pivhist[k] = pk; dinv[k] = pinv; }
            if (tval && team != pk) {
                float m = myrow[k] * pinv;      // multiplier NOT stored; col k stays
                for (int j = k + 1 + sub; j <= 65; j += 5) {
                    float newv = fmaf(-m, prow[j], myrow[j]);
                    myrow[j] = newv;
                    if (j == k + 1 && !mypivoted && k + 1 < NA)
                        atomicMax(&pmax[k+1], pivkey(newv, team));
                }
            }
            if (tval && team == pk) mypivoted = true;
            __syncthreads();
        }
    }

    // ---- direct solution (Jordan: no back-substitution) ----
    if (t < NA) wd[t] = (double)(Km[pivhist[t] * KP + 65] * dinv[t]);
    __syncthreads();

    // ---- 1x fp64-residual iterative refinement ----
    {
        // cwd = C*wd  (C = blockdiag(A, -1))
        for (int kk = w; kk < NAT; kk += 12) {
            const float* Ar = As + kk * 64;
            double acc = 0.0;
            for (int cc = lane; cc < NAT; cc += 32) acc += (double)Ar[cc] * wd[cc];
            #pragma unroll
            for (int off = 16; off; off >>= 1) acc += __shfl_down_sync(0xffffffffu, acc, off);
            if (lane == 0) cwd[kk] = acc;
        }
        if (t == 0) cwd[64] = -wd[64];
        __syncthreads();
        // rf = h - w - H*cwd  (residual per physical row)
        for (int a = w; a < NA; a += 12) {
            const float* Hr = Hs + a * HP;
            double acc = 0.0;
            for (int k2 = lane; k2 < NA; k2 += 32) acc += (double)Hr[k2] * cwd[k2];
            #pragma unroll
            for (int off = 16; off; off >>= 1) acc += __shfl_down_sync(0xffffffffu, acc, off);
            if (lane == 0) rf[a] = (float)(hd[a] - wd[a] - acc);
        }
        __syncthreads();
        // apply Jordan factors to residual: register-resident, shfl-synced
        if (t < 32) {
            float r0 = rf[t];
            float r1 = rf[t + 32];
            float r2 = (t == 0) ? rf[64] : 0.f;
            for (int k = 0; k < NA; k++) {
                int pk = pivhist[k];
                float dk = dinv[k];
                float own = (pk < 32) ? r0 : ((pk < 64) ? r1 : r2);
                float xk = __shfl_sync(0xffffffffu, own, pk & 31);
                if (t != pk)      r0 = fmaf(-(Km[t * KP + k] * dk), xk, r0);
                if (t + 32 != pk) r1 = fmaf(-(Km[(t+32) * KP + k] * dk), xk, r1);
                if (t == 0 && pk != 64) r2 = fmaf(-(Km[64 * KP + k] * dk), xk, r2);
            }
            rg[t] = r0; rg[t + 32] = r1;
            if (t == 0) rg[64] = r2;
            __syncwarp();
            for (int i = t; i < NA; i += 32)
                wd[i] += (double)(rg[pivhist[i]] * dinv[i]);
        }
        __syncthreads();
    }

    // ---- output ----
    if (t < NAT) out[mol * NAT + t] = (float)wd[t];
}

extern "C" void kernel_launch(void* const* d_in, const int* in_sizes, int n_in,
                              void* d_out, int out_size)
{
    const float* positions      = (const float*)d_in[0];
    const float* T              = (const float*)d_in[1];
    const float* eneg           = (const float*)d_in[2];
    const float* node_attrs     = (const float*)d_in[3];
    const float* total_charge   = (const float*)d_in[4];
    const float* hardness       = (const float*)d_in[6];
    const float* cov_radii      = (const float*)d_in[7];
    const int*   atomic_numbers = (const int*)d_in[8];
    const int*   edge_index     = (const int*)d_in[9];
    float* out = (float*)d_out;

    int B = in_sizes[4];
    cudaFuncSetAttribute(cheq_kernel, cudaFuncAttributeMaxDynamicSharedMemorySize, SMEM_BYTES);
    cheq_kernel<<<B, NTH, SMEM_BYTES>>>(positions, T, eneg, node_attrs, total_charge,
                                        hardness, cov_radii, atomic_numbers, edge_index, out);
}

// round 7
// speedup vs baseline: 2.2409x; 1.1781x over previous
#include <cuda_runtime.h>
#include <math.h>

typedef unsigned long long ull;

constexpr int NAT = 64;
constexpr int NE  = 512;
constexpr int NA  = 65;
constexpr int NUMEL = 10;
constexpr int CH  = 256;    // chunk width (edges)
constexpr int WCP = 260;    // Wc pitch (floats)
constexpr int HP  = 68;     // Hs pitch
constexpr int KP  = 67;     // Km pitch
constexpr int NTH = 384;    // threads per CTA (12 warps)
constexpr int NBUCK = 7;    // pivot buckets

// ---- shared memory byte offsets ----
constexpr int OFF_WD  = 0;                       // double wd[65]
constexpr int OFF_CWD = 528;                     // double cwd[65]
constexpr int OFF_WC  = 1584;                    // float Wc[65][260]
constexpr int OFF_KM  = OFF_WC;                  // float Km[65][67] (aliases Wc)
constexpr int OFF_AS  = OFF_WC + 65*WCP*4;       // 69184: float As[64][64]
constexpr int OFF_HS  = OFF_AS + 64*64*4;        // 85568: float Hs[65][68]
constexpr int OFF_SA  = OFF_HS + 65*HP*4;        // 103248: float sa[512]
constexpr int OFF_BK  = OFF_SA + 2048;           // uint buck[65*7=455] (old sg region)
constexpr int OFF_PX  = OFF_BK + 2048;
constexpr int OFF_PY  = OFF_PX + 256;
constexpr int OFF_PZ  = OFF_PY + 256;
constexpr int OFF_EN  = OFF_PZ + 256;
constexpr int OFF_DG  = OFF_EN + 256;
constexpr int OFF_RR  = OFF_DG + 256;
constexpr int OFF_RF  = OFF_RR + 256;            // float rf[68]
constexpr int OFF_RG  = OFF_RF + 272;            // float rg[68]
constexpr int OFF_DI  = OFF_RG + 272;            // float dinv[68]
constexpr int OFF_PH  = OFF_DI + 272;            // int pivhist[68]
constexpr int SMEM_BYTES = OFF_PH + 272;         // ~108 KB -> 2 CTAs/SM

__device__ __forceinline__ ull ffma2(ull a, ull b, ull c) {
    ull d;
    asm("fma.rn.f32x2 %0, %1, %2, %3;" : "=l"(d) : "l"(a), "l"(b), "l"(c));
    return d;
}
__device__ __forceinline__ ull fadd2(ull a, ull b) {
    ull d;
    asm("add.rn.f32x2 %0, %1, %2;" : "=l"(d) : "l"(a), "l"(b));
    return d;
}
__device__ __forceinline__ float2 unpack2(ull v) {
    float2 f;
    asm("mov.b64 {%0,%1}, %2;" : "=f"(f.x), "=f"(f.y) : "l"(v));
    return f;
}
// monotone packed key: |v| in top 25 bits, row in low 7
__device__ __forceinline__ unsigned int pivkey(float v, int row) {
    return (__float_as_uint(fabsf(v)) & 0xFFFFFF80u) | (unsigned int)row;
}

__global__ __launch_bounds__(NTH, 2)
void cheq_kernel(const float* __restrict__ positions,
                 const float* __restrict__ T,
                 const float* __restrict__ eneg,
                 const float* __restrict__ node_attrs,
                 const float* __restrict__ total_charge,
                 const float* __restrict__ hardness,
                 const float* __restrict__ cov_radii,
                 const int*   __restrict__ atomic_numbers,
                 const int*   __restrict__ edge_index,
                 float* __restrict__ out)
{
    extern __shared__ __align__(16) unsigned char sm[];
    double* wd  = (double*)(sm + OFF_WD);
    double* cwd = (double*)(sm + OFF_CWD);
    float* Wc  = (float*)(sm + OFF_WC);
    float* Km  = (float*)(sm + OFF_KM);
    float* As  = (float*)(sm + OFF_AS);
    float* Hs  = (float*)(sm + OFF_HS);
    float* sa  = (float*)(sm + OFF_SA);
    unsigned int* buck = (unsigned int*)(sm + OFF_BK);
    float* px  = (float*)(sm + OFF_PX);
    float* py  = (float*)(sm + OFF_PY);
    float* pz  = (float*)(sm + OFF_PZ);
    float* ens = (float*)(sm + OFF_EN);
    float* dgs = (float*)(sm + OFF_DG);
    float* rrs = (float*)(sm + OFF_RR);
    float* rf  = (float*)(sm + OFF_RF);
    float* rg  = (float*)(sm + OFF_RG);
    float* dinv= (float*)(sm + OFF_DI);
    int*   pivhist = (int*)(sm + OFF_PH);

    const int mol = blockIdx.x;
    const int t = threadIdx.x;
    const int lane = t & 31;
    const int w = t >> 5;
    const float* Tm = T + (size_t)mol * (NAT * NE);
    const float* pm = positions + mol * NAT * 3;
    const int* eim = edge_index + mol * 2 * NE;
    const float q = total_charge[mol];

    // ---- per-atom small loads + bucket zero-init ----
    if (t < NAT) {
        px[t] = pm[3*t+0]; py[t] = pm[3*t+1]; pz[t] = pm[3*t+2];
        ens[t] = eneg[mol * NAT + t];
        float r = cov_radii[atomic_numbers[mol * NAT + t]];
        rrs[t] = r * r;
        const float* na = node_attrs + (size_t)(mol * NAT + t) * NUMEL;
        float best = na[0]; int bi = 0;
        #pragma unroll
        for (int j = 1; j < NUMEL; j++) { float v = na[j]; if (v > best) { best = v; bi = j; } }
        dgs[t] = hardness[bi] + 0.5641895835477563f / r;
    }
    for (int idx = t; idx < NA * NBUCK; idx += NTH) buck[idx] = 0u;
    __syncthreads();

    // ---- A matrix (64x64, symmetric) ----
    for (int idx = t; idx < NAT * NAT; idx += NTH) {
        int i = idx >> 6, j = idx & 63;
        float v;
        if (i == j) v = dgs[i];
        else {
            float dx = px[i]-px[j], dy = py[i]-py[j], dz = pz[i]-pz[j];
            float d = sqrtf(dx*dx + dy*dy + dz*dz);
            float arg = d * rsqrtf(2.0f * (rrs[i] + rrs[j]));
            v = erff(arg) / d;
        }
        As[idx] = v;
    }

    // ---- edges: sa[e] = sqrt(1/cut), cancellation-free ----
    for (int e = t; e < NE; e += NTH) {
        int a0 = eim[e], a1 = eim[NE + e];
        float dx = px[a0]-px[a1], dy = py[a0]-py[a1], dz = pz[a0]-pz[a1];
        float ed = sqrtf(dx*dx + dy*dy + dz*dz);
        float th = 0.15707963267948966f * ed;
        float sh = sinf(0.5f * th);
        float ct = cosf(th);
        float dv = ct / (2.0f * sh * sh);
        dv = fmaxf(dv, 1e-30f);
        sa[e] = sqrtf(dv);
    }
    __syncthreads();

    // ---- syrk tile geometry (91 triangular 5x5 tiles; 12 warps x 4 groups x 2 rounds) ----
    const int g  = (lane >> 3);
    const int l8 = lane & 7;
    int tiR[2], tjR[2]; bool actR[2];
    #pragma unroll
    for (int r = 0; r < 2; r++) {
        int p = r * 48 + w * 4 + g;
        actR[r] = (p < 91);
        int pp = actR[r] ? p : 0;
        int ti = (int)((sqrtf(8.0f * pp + 1.0f) - 1.0f) * 0.5f);
        while ((ti + 1) * (ti + 2) / 2 <= pp) ++ti;
        while (ti * (ti + 1) / 2 > pp) --ti;
        tiR[r] = ti; tjR[r] = pp - ti * (ti + 1) / 2;
    }

    // ---- chunk loop: H = W W^T only (h comes from H*u later) ----
    for (int c = 0; c < 2; c++) {
        const int base = c * CH;
        for (int idx = t; idx < 64 * 64; idx += NTH) {
            int a = idx >> 6, e = (idx & 63) * 4;
            float4 v  = *(const float4*)(Tm + a * NE + base + e);
            float4 s4 = *(const float4*)(sa + base + e);
            v.x *= s4.x; v.y *= s4.y; v.z *= s4.z; v.w *= s4.w;
            *(float4*)(Wc + a * WCP + e) = v;
        }
        if (t < 64) *(float4*)(Wc + 64 * WCP + 4*t) = *(const float4*)(sa + base + 4*t);
        __syncthreads();

        #pragma unroll
        for (int r = 0; r < 2; r++) {
            const float* Wa = Wc + (tiR[r] * 5) * WCP;
            const float* Wb = Wc + (tjR[r] * 5) * WCP;
            ull acc[25];
            #pragma unroll
            for (int m = 0; m < 25; m++) acc[m] = 0ull;
            for (int e = 4 * l8; e < CH; e += 32) {
                ull a0[5], a1[5];
                #pragma unroll
                for (int i = 0; i < 5; i++) {
                    a0[i] = *(const ull*)(Wa + i * WCP + e);
                    a1[i] = *(const ull*)(Wa + i * WCP + e + 2);
                }
                #pragma unroll
                for (int j = 0; j < 5; j++) {
                    ull b0 = *(const ull*)(Wb + j * WCP + e);
                    ull b1 = *(const ull*)(Wb + j * WCP + e + 2);
                    #pragma unroll
                    for (int i = 0; i < 5; i++) {
                        acc[i*5+j] = ffma2(a0[i], b0, acc[i*5+j]);
                        acc[i*5+j] = ffma2(a1[i], b1, acc[i*5+j]);
                    }
                }
            }
            #pragma unroll
            for (int m = 0; m < 25; m++) {
                acc[m] = fadd2(acc[m], __shfl_down_sync(0xffffffffu, acc[m], 4));
                acc[m] = fadd2(acc[m], __shfl_down_sync(0xffffffffu, acc[m], 2));
                acc[m] = fadd2(acc[m], __shfl_down_sync(0xffffffffu, acc[m], 1));
            }
            if (actR[r] && l8 == 0) {
                int ti = tiR[r], tj = tjR[r];
                #pragma unroll
                for (int i = 0; i < 5; i++)
                    #pragma unroll
                    for (int j = 0; j < 5; j++) {
                        float2 f = unpack2(acc[i*5+j]);
                        float v = f.x + f.y;
                        int lo = (ti*5+i) * HP + (tj*5+j);
                        if (c == 0) Hs[lo] = v; else Hs[lo] += v;
                        if (ti != tj) {
                            int up = (tj*5+j) * HP + (ti*5+i);
                            if (c == 0) Hs[up] = v; else Hs[up] += v;
                        }
                    }
            }
        }
        __syncthreads();
    }

    // ---- K = I + H*C (f32x2), cols 64/65, rhs = -H*u (fp64), seed pivot buckets ----
    // rhs: h = W*sg = -H*u with u = [eneg; q]; lane0 writes Km col 65 directly.
    for (int a = w; a < NA; a += 12) {
        const float* Hr = Hs + a * HP;
        double acc = 0.0;
        for (int k2 = lane; k2 < NA; k2 += 32) {
            float uk = (k2 < 64) ? ens[k2] : q;
            acc += (double)Hr[k2] * (double)uk;
        }
        #pragma unroll
        for (int off = 16; off; off >>= 1) acc += __shfl_down_sync(0xffffffffu, acc, off);
        if (lane == 0) Km[a * KP + 65] = (float)(-acc);
    }
    if (t < NA)
        Km[t * KP + 64] = ((t == 64) ? 1.0f : 0.0f) - Hs[t * HP + 64];
    for (int idx = t; idx < NA * 16; idx += NTH) {
        int a = idx >> 4, c0 = (idx & 15) * 4;
        const ulonglong2* Hr2 = (const ulonglong2*)(Hs + a * HP);
        ull q0 = 0, q1 = 0, q2 = 0, q3 = 0;
        #pragma unroll 4
        for (int kq = 0; kq < 16; kq++) {
            ulonglong2 h2 = Hr2[kq];
            ulonglong2 A0 = *(const ulonglong2*)(As + (c0+0) * 64 + kq * 4);
            ulonglong2 A1 = *(const ulonglong2*)(As + (c0+1) * 64 + kq * 4);
            ulonglong2 A2 = *(const ulonglong2*)(As + (c0+2) * 64 + kq * 4);
            ulonglong2 A3 = *(const ulonglong2*)(As + (c0+3) * 64 + kq * 4);
            q0 = ffma2(h2.x, A0.x, q0); q0 = ffma2(h2.y, A0.y, q0);
            q1 = ffma2(h2.x, A1.x, q1); q1 = ffma2(h2.y, A1.y, q1);
            q2 = ffma2(h2.x, A2.x, q2); q2 = ffma2(h2.y, A2.y, q2);
            q3 = ffma2(h2.x, A3.x, q3); q3 = ffma2(h2.y, A3.y, q3);
        }
        float2 f0 = unpack2(q0), f1 = unpack2(q1), f2 = unpack2(q2), f3 = unpack2(q3);
        float v0 = f0.x + f0.y + ((a == c0+0) ? 1.0f : 0.0f);
        Km[a * KP + c0 + 0] = v0;
        Km[a * KP + c0 + 1] = f1.x + f1.y + ((a == c0+1) ? 1.0f : 0.0f);
        Km[a * KP + c0 + 2] = f2.x + f2.y + ((a == c0+2) ? 1.0f : 0.0f);
        Km[a * KP + c0 + 3] = f3.x + f3.y + ((a == c0+3) ? 1.0f : 0.0f);
        if (c0 == 0) atomicMax(&buck[a % NBUCK], pivkey(v0, a));   // seed step-0 pivots
    }
    __syncthreads();

    // ---- Gauss-Jordan, implicit pivoting, bucketed pivot select: 1 barrier/step ----
    {
        const int team = t / 5;
        const int sub  = t - team * 5;
        const bool tval = (t < 325);
        const int mybuck = team % NBUCK;
        bool mypivoted = false;
        float* myrow = Km + team * KP;
        for (int k = 0; k < NA; k++) {
            unsigned int bk = buck[k * NBUCK];
            #pragma unroll
            for (int b = 1; b < NBUCK; b++) {
                unsigned int v = buck[k * NBUCK + b];
                if (v > bk) bk = v;
            }
            int pk = (int)(bk & 0x7Fu);
            const float* prow = Km + pk * KP;
            float pinv = 1.0f / prow[k];
            if (t == 0) { pivhist[k] = pk; dinv[k] = pinv; }
            if (tval && team != pk) {
                float m = myrow[k] * pinv;
                for (int j = k + 1 + sub; j <= 65; j += 5) {
                    float newv = fmaf(-m, prow[j], myrow[j]);
                    myrow[j] = newv;
                    if (j == k + 1 && !mypivoted && k + 1 < NA)
                        atomicMax(&buck[(k+1) * NBUCK + mybuck], pivkey(newv, team));
                }
            }
            if (tval && team == pk) mypivoted = true;
            __syncthreads();
        }
    }

    // ---- direct solution (Jordan) ----
    if (t < NA) wd[t] = (double)(Km[pivhist[t] * KP + 65] * dinv[t]);
    __syncthreads();

    // ---- 1x fp64-residual refinement: rf = -w - H*(u + C*w) ----
    {
        for (int kk = w; kk < NAT; kk += 12) {
            const float* Ar = As + kk * 64;
            double acc = 0.0;
            for (int cc = lane; cc < NAT; cc += 32) acc += (double)Ar[cc] * wd[cc];
            #pragma unroll
            for (int off = 16; off; off >>= 1) acc += __shfl_down_sync(0xffffffffu, acc, off);
            if (lane == 0) cwd[kk] = acc;
        }
        if (t == 0) cwd[64] = -wd[64];
        __syncthreads();
        for (int a = w; a < NA; a += 12) {
            const float* Hr = Hs + a * HP;
            double acc = 0.0;
            for (int k2 = lane; k2 < NA; k2 += 32) {
                double uk = (k2 < 64) ? (double)ens[k2] : (double)q;
                acc += (double)Hr[k2] * (cwd[k2] + uk);
            }
            #pragma unroll
            for (int off = 16; off; off >>= 1) acc += __shfl_down_sync(0xffffffffu, acc, off);
            if (lane == 0) rf[a] = (float)(-wd[a] - acc);
        }
        __syncthreads();
        // apply Jordan factors to residual: register-resident, shfl-synced (warp 0)
        if (t < 32) {
            float r0 = rf[t];
            float r1 = rf[t + 32];
            float r2 = (t == 0) ? rf[64] : 0.f;
            for (int k = 0; k < NA; k++) {
                int pk = pivhist[k];
                float dk = dinv[k];
                float own = (pk < 32) ? r0 : ((pk < 64) ? r1 : r2);
                float xk = __shfl_sync(0xffffffffu, own, pk & 31);
                if (t != pk)      r0 = fmaf(-(Km[t * KP + k] * dk), xk, r0);
                if (t + 32 != pk) r1 = fmaf(-(Km[(t+32) * KP + k] * dk), xk, r1);
                if (t == 0 && pk != 64) r2 = fmaf(-(Km[64 * KP + k] * dk), xk, r2);
            }
            rg[t] = r0; rg[t + 32] = r1;
            if (t == 0) rg[64] = r2;
            __syncwarp();
            for (int i = t; i < NA; i += 32)
                wd[i] += (double)(rg[pivhist[i]] * dinv[i]);
        }
        __syncthreads();
    }

    // ---- output ----
    if (t < NAT) out[mol * NAT + t] = (float)wd[t];
}

extern "C" void kernel_launch(void* const* d_in, const int* in_sizes, int n_in,
                              void* d_out, int out_size)
{
    const float* positions      = (const float*)d_in[0];
    const float* T              = (const float*)d_in[1];
    const float* eneg           = (const float*)d_in[2];
    const float* node_attrs     = (const float*)d_in[3];
    const float* total_charge   = (const float*)d_in[4];
    const float* hardness       = (const float*)d_in[6];
    const float* cov_radii      = (const float*)d_in[7];
    const int*   atomic_numbers = (const int*)d_in[8];
    const int*   edge_index     = (const int*)d_in[9];
    float* out = (float*)d_out;

    int B = in_sizes[4];
    cudaFuncSetAttribute(cheq_kernel, cudaFuncAttributeMaxDynamicSharedMemorySize, SMEM_BYTES);
    cheq_kernel<<<B, NTH, SMEM_BYTES>>>(positions, T, eneg, node_attrs, total_charge,
                                        hardness, cov_radii, atomic_numbers, edge_index, out);
}

// round 8
// speedup vs baseline: 2.2623x; 1.0095x over previous
#include <cuda_runtime.h>
#include <math.h>

typedef unsigned long long ull;

constexpr int NAT = 64;
constexpr int NE  = 512;
constexpr int NA  = 65;
constexpr int NUMEL = 10;
constexpr int CH  = 256;    // chunk width (edges)
constexpr int WCP = 260;    // Wc pitch (floats)
constexpr int HP  = 68;     // Hs pitch
constexpr int KP  = 67;     // Km pitch
constexpr int FP  = 68;     // Fm pitch
constexpr int NTH = 384;    // threads per CTA (12 warps)

// ---- shared memory byte offsets ----
constexpr int OFF_WD  = 0;                       // double wd[65]
constexpr int OFF_CWD = 528;                     // double cwd[65]
constexpr int OFF_WC  = 1584;                    // float Wc[65][260]
constexpr int OFF_KM  = OFF_WC;                  // float Km[65][67]  (aliases Wc)
constexpr int OFF_FM  = OFF_WC + 65*KP*4 + 16;   // float Fm[65][68]  (aliases Wc, after Km)
constexpr int OFF_AS  = OFF_WC + 65*WCP*4;       // float As[64][64]
constexpr int OFF_HS  = OFF_AS + 64*64*4;        // float Hs[65][68]
constexpr int OFF_SA  = OFF_HS + 65*HP*4;        // float sa[512]
constexpr int OFF_PX  = OFF_SA + 2048;
constexpr int OFF_PY  = OFF_PX + 256;
constexpr int OFF_PZ  = OFF_PY + 256;
constexpr int OFF_EN  = OFF_PZ + 256;
constexpr int OFF_DG  = OFF_EN + 256;
constexpr int OFF_RR  = OFF_DG + 256;
constexpr int OFF_RF  = OFF_RR + 256;            // float rf[68]
constexpr int OFF_RG  = OFF_RF + 272;            // float rg[68]
constexpr int OFF_DI  = OFF_RG + 272;            // float dinv[68]
constexpr int OFF_PH  = OFF_DI + 272;            // int pivhist[68]
constexpr int SMEM_BYTES = OFF_PH + 272;         // ~106 KB -> 2 CTAs/SM

static_assert(OFF_FM + 65*FP*4 <= OFF_AS, "Fm must fit in Wc region after Km");

__device__ __forceinline__ ull ffma2(ull a, ull b, ull c) {
    ull d;
    asm("fma.rn.f32x2 %0, %1, %2, %3;" : "=l"(d) : "l"(a), "l"(b), "l"(c));
    return d;
}
__device__ __forceinline__ ull fadd2(ull a, ull b) {
    ull d;
    asm("add.rn.f32x2 %0, %1, %2;" : "=l"(d) : "l"(a), "l"(b));
    return d;
}
__device__ __forceinline__ float2 unpack2(ull v) {
    float2 f;
    asm("mov.b64 {%0,%1}, %2;" : "=f"(f.x), "=f"(f.y) : "l"(v));
    return f;
}
// monotone packed key: |v| in top 25 bits, row in low 7
__device__ __forceinline__ unsigned int pivkey(float v, int row) {
    return (__float_as_uint(fabsf(v)) & 0xFFFFFF80u) | (unsigned int)row;
}

__global__ __launch_bounds__(NTH, 2)
void cheq_kernel(const float* __restrict__ positions,
                 const float* __restrict__ T,
                 const float* __restrict__ eneg,
                 const float* __restrict__ node_attrs,
                 const float* __restrict__ total_charge,
                 const float* __restrict__ hardness,
                 const float* __restrict__ cov_radii,
                 const int*   __restrict__ atomic_numbers,
                 const int*   __restrict__ edge_index,
                 float* __restrict__ out)
{
    extern __shared__ __align__(16) unsigned char sm[];
    double* wd  = (double*)(sm + OFF_WD);
    double* cwd = (double*)(sm + OFF_CWD);
    float* Wc  = (float*)(sm + OFF_WC);
    float* Km  = (float*)(sm + OFF_KM);
    float* Fm  = (float*)(sm + OFF_FM);
    float* As  = (float*)(sm + OFF_AS);
    float* Hs  = (float*)(sm + OFF_HS);
    float* sa  = (float*)(sm + OFF_SA);
    float* px  = (float*)(sm + OFF_PX);
    float* py  = (float*)(sm + OFF_PY);
    float* pz  = (float*)(sm + OFF_PZ);
    float* ens = (float*)(sm + OFF_EN);
    float* dgs = (float*)(sm + OFF_DG);
    float* rrs = (float*)(sm + OFF_RR);
    float* rf  = (float*)(sm + OFF_RF);
    float* rg  = (float*)(sm + OFF_RG);
    float* dinv= (float*)(sm + OFF_DI);
    int*   pivhist = (int*)(sm + OFF_PH);

    const int mol = blockIdx.x;
    const int t = threadIdx.x;
    const int lane = t & 31;
    const int w = t >> 5;
    const float* Tm = T + (size_t)mol * (NAT * NE);
    const float* pm = positions + mol * NAT * 3;
    const int* eim = edge_index + mol * 2 * NE;
    const float q = total_charge[mol];

    // ---- per-atom small loads ----
    if (t < NAT) {
        px[t] = pm[3*t+0]; py[t] = pm[3*t+1]; pz[t] = pm[3*t+2];
        ens[t] = eneg[mol * NAT + t];
        float r = cov_radii[atomic_numbers[mol * NAT + t]];
        rrs[t] = r * r;
        const float* na = node_attrs + (size_t)(mol * NAT + t) * NUMEL;
        float best = na[0]; int bi = 0;
        #pragma unroll
        for (int j = 1; j < NUMEL; j++) { float v = na[j]; if (v > best) { best = v; bi = j; } }
        dgs[t] = hardness[bi] + 0.5641895835477563f / r;
    }
    __syncthreads();

    // ---- A matrix (64x64, symmetric) ----
    for (int idx = t; idx < NAT * NAT; idx += NTH) {
        int i = idx >> 6, j = idx & 63;
        float v;
        if (i == j) v = dgs[i];
        else {
            float dx = px[i]-px[j], dy = py[i]-py[j], dz = pz[i]-pz[j];
            float d = sqrtf(dx*dx + dy*dy + dz*dz);
            float arg = d * rsqrtf(2.0f * (rrs[i] + rrs[j]));
            v = erff(arg) / d;
        }
        As[idx] = v;
    }

    // ---- edges: sa[e] = sqrt(1/cut), cancellation-free ----
    for (int e = t; e < NE; e += NTH) {
        int a0 = eim[e], a1 = eim[NE + e];
        float dx = px[a0]-px[a1], dy = py[a0]-py[a1], dz = pz[a0]-pz[a1];
        float ed = sqrtf(dx*dx + dy*dy + dz*dz);
        float th = 0.15707963267948966f * ed;
        float sh = sinf(0.5f * th);
        float ct = cosf(th);
        float dv = ct / (2.0f * sh * sh);
        dv = fmaxf(dv, 1e-30f);
        sa[e] = sqrtf(dv);
    }
    __syncthreads();

    // ---- syrk tile geometry (91 triangular 5x5 tiles; 12 warps x 4 groups x 2 rounds) ----
    const int g  = (lane >> 3);
    const int l8 = lane & 7;
    int tiR[2], tjR[2]; bool actR[2];
    #pragma unroll
    for (int r = 0; r < 2; r++) {
        int p = r * 48 + w * 4 + g;
        actR[r] = (p < 91);
        int pp = actR[r] ? p : 0;
        int ti = (int)((sqrtf(8.0f * pp + 1.0f) - 1.0f) * 0.5f);
        while ((ti + 1) * (ti + 2) / 2 <= pp) ++ti;
        while (ti * (ti + 1) / 2 > pp) --ti;
        tiR[r] = ti; tjR[r] = pp - ti * (ti + 1) / 2;
    }

    // ---- chunk loop: H = W W^T ----
    for (int c = 0; c < 2; c++) {
        const int base = c * CH;
        for (int idx = t; idx < 64 * 64; idx += NTH) {
            int a = idx >> 6, e = (idx & 63) * 4;
            float4 v  = *(const float4*)(Tm + a * NE + base + e);
            float4 s4 = *(const float4*)(sa + base + e);
            v.x *= s4.x; v.y *= s4.y; v.z *= s4.z; v.w *= s4.w;
            *(float4*)(Wc + a * WCP + e) = v;
        }
        if (t < 64) *(float4*)(Wc + 64 * WCP + 4*t) = *(const float4*)(sa + base + 4*t);
        __syncthreads();

        #pragma unroll
        for (int r = 0; r < 2; r++) {
            const float* Wa = Wc + (tiR[r] * 5) * WCP;
            const float* Wb = Wc + (tjR[r] * 5) * WCP;
            ull acc[25];
            #pragma unroll
            for (int m = 0; m < 25; m++) acc[m] = 0ull;
            for (int e = 4 * l8; e < CH; e += 32) {
                ull a0[5], a1[5];
                #pragma unroll
                for (int i = 0; i < 5; i++) {
                    a0[i] = *(const ull*)(Wa + i * WCP + e);
                    a1[i] = *(const ull*)(Wa + i * WCP + e + 2);
                }
                #pragma unroll
                for (int j = 0; j < 5; j++) {
                    ull b0 = *(const ull*)(Wb + j * WCP + e);
                    ull b1 = *(const ull*)(Wb + j * WCP + e + 2);
                    #pragma unroll
                    for (int i = 0; i < 5; i++) {
                        acc[i*5+j] = ffma2(a0[i], b0, acc[i*5+j]);
                        acc[i*5+j] = ffma2(a1[i], b1, acc[i*5+j]);
                    }
                }
            }
            #pragma unroll
            for (int m = 0; m < 25; m++) {
                acc[m] = fadd2(acc[m], __shfl_down_sync(0xffffffffu, acc[m], 4));
                acc[m] = fadd2(acc[m], __shfl_down_sync(0xffffffffu, acc[m], 2));
                acc[m] = fadd2(acc[m], __shfl_down_sync(0xffffffffu, acc[m], 1));
            }
            if (actR[r] && l8 == 0) {
                int ti = tiR[r], tj = tjR[r];
                #pragma unroll
                for (int i = 0; i < 5; i++)
                    #pragma unroll
                    for (int j = 0; j < 5; j++) {
                        float2 f = unpack2(acc[i*5+j]);
                        float v = f.x + f.y;
                        int lo = (ti*5+i) * HP + (tj*5+j);
                        if (c == 0) Hs[lo] = v; else Hs[lo] += v;
                        if (ti != tj) {
                            int up = (tj*5+j) * HP + (ti*5+i);
                            if (c == 0) Hs[up] = v; else Hs[up] += v;
                        }
                    }
            }
        }
        __syncthreads();
    }

    // ---- K = I + H*C (f32x2); col 64; rhs col 65 = -H*u (fp64) ----
    for (int a = w; a < NA; a += 12) {
        const float* Hr = Hs + a * HP;
        double acc = 0.0;
        for (int k2 = lane; k2 < NA; k2 += 32) {
            float uk = (k2 < 64) ? ens[k2] : q;
            acc += (double)Hr[k2] * (double)uk;
        }
        #pragma unroll
        for (int off = 16; off; off >>= 1) acc += __shfl_down_sync(0xffffffffu, acc, off);
        if (lane == 0) Km[a * KP + 65] = (float)(-acc);
    }
    if (t < NA)
        Km[t * KP + 64] = ((t == 64) ? 1.0f : 0.0f) - Hs[t * HP + 64];
    for (int idx = t; idx < NA * 16; idx += NTH) {
        int a = idx >> 4, c0 = (idx & 15) * 4;
        const ulonglong2* Hr2 = (const ulonglong2*)(Hs + a * HP);
        ull q0 = 0, q1 = 0, q2 = 0, q3 = 0;
        #pragma unroll 4
        for (int kq = 0; kq < 16; kq++) {
            ulonglong2 h2 = Hr2[kq];
            ulonglong2 A0 = *(const ulonglong2*)(As + (c0+0) * 64 + kq * 4);
            ulonglong2 A1 = *(const ulonglong2*)(As + (c0+1) * 64 + kq * 4);
            ulonglong2 A2 = *(const ulonglong2*)(As + (c0+2) * 64 + kq * 4);
            ulonglong2 A3 = *(const ulonglong2*)(As + (c0+3) * 64 + kq * 4);
            q0 = ffma2(h2.x, A0.x, q0); q0 = ffma2(h2.y, A0.y, q0);
            q1 = ffma2(h2.x, A1.x, q1); q1 = ffma2(h2.y, A1.y, q1);
            q2 = ffma2(h2.x, A2.x, q2); q2 = ffma2(h2.y, A2.y, q2);
            q3 = ffma2(h2.x, A3.x, q3); q3 = ffma2(h2.y, A3.y, q3);
        }
        float2 f0 = unpack2(q0), f1 = unpack2(q1), f2 = unpack2(q2), f3 = unpack2(q3);
        Km[a * KP + c0 + 0] = f0.x + f0.y + ((a == c0+0) ? 1.0f : 0.0f);
        Km[a * KP + c0 + 1] = f1.x + f1.y + ((a == c0+1) ? 1.0f : 0.0f);
        Km[a * KP + c0 + 2] = f2.x + f2.y + ((a == c0+2) ? 1.0f : 0.0f);
        Km[a * KP + c0 + 3] = f3.x + f3.y + ((a == c0+3) ? 1.0f : 0.0f);
    }
    __syncthreads();

    // ---- Gauss-Jordan, register-resident columns, shfl pivot rows ----
    // Warp w owns columns j = w + 12*c (c < cols0). Lane holds rows lane, lane+32,
    // and (lane==0) row 64. Fm[k][row] stores the published col-k values = the
    // Jordan factor matrix (reused by refinement).
    {
        const int cols0 = (w < 6) ? 6 : 5;     // cols 0..65: warps 0-5 own 6, 6-11 own 5
        float cv0[6], cv1[6], cv2[6];
        #pragma unroll
        for (int c = 0; c < 6; c++) {
            cv0[c] = 0.f; cv1[c] = 0.f; cv2[c] = 0.f;
            int j = w + 12 * c;
            if (c < cols0) {
                cv0[c] = Km[lane * KP + j];
                cv1[c] = Km[(lane + 32) * KP + j];
                if (lane == 0) cv2[c] = Km[64 * KP + j];
            }
        }
        bool piv0 = false, piv1 = false, piv2 = false;
        if (w == 0) {                           // publish col 0 + select pivot 0
            Fm[lane] = cv0[0];
            Fm[lane + 32] = cv1[0];
            if (lane == 0) Fm[64] = cv2[0];
            unsigned int key = pivkey(cv0[0], lane);
            unsigned int k1  = pivkey(cv1[0], lane + 32);
            if (k1 > key) key = k1;
            if (lane == 0) { unsigned int k2 = pivkey(cv2[0], 64); if (k2 > key) key = k2; }
            #pragma unroll
            for (int o = 16; o; o >>= 1) {
                unsigned int ov = __shfl_xor_sync(0xffffffffu, key, o);
                if (ov > key) key = ov;
            }
            int prow = (int)(key & 0x7Fu);
            float src = (prow < 32) ? cv0[0] : ((prow < 64) ? cv1[0] : cv2[0]);
            float pval = __shfl_sync(0xffffffffu, src, prow & 31);
            if (lane == 0) { pivhist[0] = prow; dinv[0] = 1.0f / pval; }
        }
        __syncthreads();

        for (int k = 0; k < NA; k++) {
            int pk = pivhist[k];
            float dk = dinv[k];
            float m0 = Fm[k * FP + lane] * dk;
            float m1 = Fm[k * FP + lane + 32] * dk;
            float m2 = Fm[k * FP + 64] * dk;
            if (lane == pk)      { m0 = 0.f; piv0 = true; }
            if (lane + 32 == pk) { m1 = 0.f; piv1 = true; }
            if (pk == 64)        { m2 = 0.f; piv2 = true; }
            #pragma unroll
            for (int c = 0; c < 6; c++) {
                int j = w + 12 * c;
                if (c < cols0 && j > k) {       // warp-uniform predicate
                    float src = (pk < 32) ? cv0[c] : ((pk < 64) ? cv1[c] : cv2[c]);
                    float pv = __shfl_sync(0xffffffffu, src, pk & 31);
                    cv0[c] = fmaf(-m0, pv, cv0[c]);
                    cv1[c] = fmaf(-m1, pv, cv1[c]);
                    cv2[c] = fmaf(-m2, pv, cv2[c]);
                }
            }
            int nk = k + 1;
            if (nk < NA && w == (nk % 12)) {    // publish col nk + select pivot nk
                #pragma unroll
                for (int c = 0; c < 6; c++) {
                    if (c < cols0 && (w + 12 * c) == nk) {
                        float v0 = cv0[c], v1 = cv1[c], v2 = cv2[c];
                        Fm[nk * FP + lane] = v0;
                        Fm[nk * FP + lane + 32] = v1;
                        if (lane == 0) Fm[nk * FP + 64] = v2;
                        unsigned int key = piv0 ? 0u : pivkey(v0, lane);
                        unsigned int k1  = piv1 ? 0u : pivkey(v1, lane + 32);
                        if (k1 > key) key = k1;
                        if (lane == 0 && !piv2) {
                            unsigned int k2 = pivkey(v2, 64);
                            if (k2 > key) key = k2;
                        }
                        #pragma unroll
                        for (int o = 16; o; o >>= 1) {
                            unsigned int ov = __shfl_xor_sync(0xffffffffu, key, o);
                            if (ov > key) key = ov;
                        }
                        int prow = (int)(key & 0x7Fu);
                        float src = (prow < 32) ? v0 : ((prow < 64) ? v1 : v2);
                        float pval = __shfl_sync(0xffffffffu, src, prow & 31);
                        if (lane == 0) { pivhist[nk] = prow; dinv[nk] = 1.0f / pval; }
                    }
                }
            }
            __syncthreads();
        }

        // rhs col 65 lives in warp 5 (c = 5): publish to rf
        if (w == 5) {
            rf[lane] = cv0[5];
            rf[lane + 32] = cv1[5];
            if (lane == 0) rf[64] = cv2[5];
        }
        __syncthreads();
    }

    // ---- direct solution (Jordan) ----
    if (t < NA) wd[t] = (double)(rf[pivhist[t]] * dinv[t]);
    __syncthreads();

    // ---- 1x fp64-residual refinement: rf = -w - H*(u + C*w) ----
    {
        for (int kk = w; kk < NAT; kk += 12) {
            const float* Ar = As + kk * 64;
            double acc = 0.0;
            for (int cc = lane; cc < NAT; cc += 32) acc += (double)Ar[cc] * wd[cc];
            #pragma unroll
            for (int off = 16; off; off >>= 1) acc += __shfl_down_sync(0xffffffffu, acc, off);
            if (lane == 0) cwd[kk] = acc;
        }
        if (t == 0) cwd[64] = -wd[64];
        __syncthreads();
        for (int a = w; a < NA; a += 12) {
            const float* Hr = Hs + a * HP;
            double acc = 0.0;
            for (int k2 = lane; k2 < NA; k2 += 32) {
                double uk = (k2 < 64) ? (double)ens[k2] : (double)q;
                acc += (double)Hr[k2] * (cwd[k2] + uk);
            }
            #pragma unroll
            for (int off = 16; off; off >>= 1) acc += __shfl_down_sync(0xffffffffu, acc, off);
            if (lane == 0) rf[a] = (float)(-wd[a] - acc);
        }
        __syncthreads();
        // apply Jordan factors (from Fm) to residual: register-resident, warp 0
        if (t < 32) {
            float r0 = rf[t];
            float r1 = rf[t + 32];
            float r2 = (t == 0) ? rf[64] : 0.f;
            for (int k = 0; k < NA; k++) {
                int pk = pivhist[k];
                float dk = dinv[k];
                float own = (pk < 32) ? r0 : ((pk < 64) ? r1 : r2);
                float xk = __shfl_sync(0xffffffffu, own, pk & 31);
                if (t != pk)      r0 = fmaf(-(Fm[k * FP + t] * dk), xk, r0);
                if (t + 32 != pk) r1 = fmaf(-(Fm[k * FP + t + 32] * dk), xk, r1);
                if (t == 0 && pk != 64) r2 = fmaf(-(Fm[k * FP + 64] * dk), xk, r2);
            }
            rg[t] = r0; rg[t + 32] = r1;
            if (t == 0) rg[64] = r2;
            __syncwarp();
            for (int i = t; i < NA; i += 32)
                wd[i] += (double)(rg[pivhist[i]] * dinv[i]);
        }
        __syncthreads();
    }

    // ---- output ----
    if (t < NAT) out[mol * NAT + t] = (float)wd[t];
}

extern "C" void kernel_launch(void* const* d_in, const int* in_sizes, int n_in,
                              void* d_out, int out_size)
{
    const float* positions      = (const float*)d_in[0];
    const float* T              = (const float*)d_in[1];
    const float* eneg           = (const float*)d_in[2];
    const float* node_attrs     = (const float*)d_in[3];
    const float* total_charge   = (const float*)d_in[4];
    const float* hardness       = (const float*)d_in[6];
    const float* cov_radii      = (const float*)d_in[7];
    const int*   atomic_numbers = (const int*)d_in[8];
    const int*   edge_index     = (const int*)d_in[9];
    float* out = (float*)d_out;

    int B = in_sizes[4];
    cudaFuncSetAttribute(cheq_kernel, cudaFuncAttributeMaxDynamicSharedMemorySize, SMEM_BYTES);
    cheq_kernel<<<B, NTH, SMEM_BYTES>>>(positions, T, eneg, node_attrs, total_charge,
                                        hardness, cov_radii, atomic_numbers, edge_index, out);
}

// round 9
// speedup vs baseline: 3.1880x; 1.4092x over previous
#include <cuda_runtime.h>
#include <math.h>

typedef unsigned long long ull;

constexpr int NAT = 64;
constexpr int NE  = 512;
constexpr int NA  = 65;
constexpr int NUMEL = 10;
constexpr int CH  = 256;    // chunk width (edges)
constexpr int WCP = 260;    // Wc pitch (floats)
constexpr int HP  = 68;     // Hs pitch
constexpr int KP  = 68;     // Km pitch (16B-aligned rows)
constexpr int FP  = 68;     // Fm pitch
constexpr int NTH = 384;    // threads per CTA (12 warps)

// ---- shared memory byte offsets ----
constexpr int OFF_WD  = 0;                       // double wd[65]
constexpr int OFF_CWD = 528;                     // double cwd[65]
constexpr int OFF_WC  = 1584;                    // float Wc[65][260]
constexpr int OFF_KM  = OFF_WC;                  // float Km[65][68]  (aliases Wc)
constexpr int OFF_FM  = OFF_WC + 65*KP*4 + 16;   // float Fm[65][68]  (aliases Wc, after Km)
constexpr int OFF_AS  = OFF_WC + 65*WCP*4;       // float As[64][64]
constexpr int OFF_HS  = OFF_AS + 64*64*4;        // float Hs[65][68]
constexpr int OFF_SA  = OFF_HS + 65*HP*4;        // float sa[512]
constexpr int OFF_PX  = OFF_SA + 2048;
constexpr int OFF_PY  = OFF_PX + 256;
constexpr int OFF_PZ  = OFF_PY + 256;
constexpr int OFF_EN  = OFF_PZ + 256;
constexpr int OFF_DG  = OFF_EN + 256;
constexpr int OFF_RR  = OFF_DG + 256;
constexpr int OFF_RF  = OFF_RR + 256;            // float rf[68]
constexpr int OFF_RG  = OFF_RF + 272;            // float rg[68]
constexpr int OFF_DI  = OFF_RG + 272;            // float dinv[68]
constexpr int OFF_PH  = OFF_DI + 272;            // int pivhist[68]
constexpr int SMEM_BYTES = OFF_PH + 272;         // ~106 KB -> 2 CTAs/SM

static_assert(OFF_FM + 65*FP*4 <= OFF_AS, "Fm must fit in Wc region after Km");

__device__ __forceinline__ ull ffma2(ull a, ull b, ull c) {
    ull d;
    asm("fma.rn.f32x2 %0, %1, %2, %3;" : "=l"(d) : "l"(a), "l"(b), "l"(c));
    return d;
}
__device__ __forceinline__ ull fadd2(ull a, ull b) {
    ull d;
    asm("add.rn.f32x2 %0, %1, %2;" : "=l"(d) : "l"(a), "l"(b));
    return d;
}
__device__ __forceinline__ float2 unpack2(ull v) {
    float2 f;
    asm("mov.b64 {%0,%1}, %2;" : "=f"(f.x), "=f"(f.y) : "l"(v));
    return f;
}
__device__ __forceinline__ ull dup2(float f) {
    ull d;
    asm("mov.b64 %0, {%1, %1};" : "=l"(d) : "f"(f));
    return d;
}
// monotone packed key: |v| in top 25 bits, row in low 7
__device__ __forceinline__ unsigned int pivkey(float v, int row) {
    return (__float_as_uint(fabsf(v)) & 0xFFFFFF80u) | (unsigned int)row;
}

__global__ __launch_bounds__(NTH, 2)
void cheq_kernel(const float* __restrict__ positions,
                 const float* __restrict__ T,
                 const float* __restrict__ eneg,
                 const float* __restrict__ node_attrs,
                 const float* __restrict__ total_charge,
                 const float* __restrict__ hardness,
                 const float* __restrict__ cov_radii,
                 const int*   __restrict__ atomic_numbers,
                 const int*   __restrict__ edge_index,
                 float* __restrict__ out)
{
    extern __shared__ __align__(16) unsigned char sm[];
    double* wd  = (double*)(sm + OFF_WD);
    double* cwd = (double*)(sm + OFF_CWD);
    float* Wc  = (float*)(sm + OFF_WC);
    float* Km  = (float*)(sm + OFF_KM);
    float* Fm  = (float*)(sm + OFF_FM);
    float* As  = (float*)(sm + OFF_AS);
    float* Hs  = (float*)(sm + OFF_HS);
    float* sa  = (float*)(sm + OFF_SA);
    float* px  = (float*)(sm + OFF_PX);
    float* py  = (float*)(sm + OFF_PY);
    float* pz  = (float*)(sm + OFF_PZ);
    float* ens = (float*)(sm + OFF_EN);
    float* dgs = (float*)(sm + OFF_DG);
    float* rrs = (float*)(sm + OFF_RR);
    float* rf  = (float*)(sm + OFF_RF);
    float* rg  = (float*)(sm + OFF_RG);
    float* dinv= (float*)(sm + OFF_DI);
    int*   pivhist = (int*)(sm + OFF_PH);

    const int mol = blockIdx.x;
    const int t = threadIdx.x;
    const int lane = t & 31;
    const int w = t >> 5;
    const float* Tm = T + (size_t)mol * (NAT * NE);
    const float* pm = positions + mol * NAT * 3;
    const int* eim = edge_index + mol * 2 * NE;
    const float q = total_charge[mol];

    // ---- per-atom small loads ----
    if (t < NAT) {
        px[t] = pm[3*t+0]; py[t] = pm[3*t+1]; pz[t] = pm[3*t+2];
        ens[t] = eneg[mol * NAT + t];
        float r = cov_radii[atomic_numbers[mol * NAT + t]];
        rrs[t] = r * r;
        const float* na = node_attrs + (size_t)(mol * NAT + t) * NUMEL;
        float best = na[0]; int bi = 0;
        #pragma unroll
        for (int j = 1; j < NUMEL; j++) { float v = na[j]; if (v > best) { best = v; bi = j; } }
        dgs[t] = hardness[bi] + 0.5641895835477563f / r;
    }
    __syncthreads();

    // ---- A matrix (64x64, symmetric) ----
    for (int idx = t; idx < NAT * NAT; idx += NTH) {
        int i = idx >> 6, j = idx & 63;
        float v;
        if (i == j) v = dgs[i];
        else {
            float dx = px[i]-px[j], dy = py[i]-py[j], dz = pz[i]-pz[j];
            float d = sqrtf(dx*dx + dy*dy + dz*dz);
            float arg = d * rsqrtf(2.0f * (rrs[i] + rrs[j]));
            v = erff(arg) / d;
        }
        As[idx] = v;
    }

    // ---- edges: sa[e] = sqrt(1/cut), cancellation-free ----
    for (int e = t; e < NE; e += NTH) {
        int a0 = eim[e], a1 = eim[NE + e];
        float dx = px[a0]-px[a1], dy = py[a0]-py[a1], dz = pz[a0]-pz[a1];
        float ed = sqrtf(dx*dx + dy*dy + dz*dz);
        float th = 0.15707963267948966f * ed;
        float sh = sinf(0.5f * th);
        float ct = cosf(th);
        float dv = ct / (2.0f * sh * sh);
        dv = fmaxf(dv, 1e-30f);
        sa[e] = sqrtf(dv);
    }
    __syncthreads();

    // ---- syrk tile geometry (91 triangular 5x5 tiles; 12 warps x 4 groups x 2 rounds) ----
    const int g  = (lane >> 3);
    const int l8 = lane & 7;
    int tiR[2], tjR[2]; bool actR[2];
    #pragma unroll
    for (int r = 0; r < 2; r++) {
        int p = r * 48 + w * 4 + g;
        actR[r] = (p < 91);
        int pp = actR[r] ? p : 0;
        int ti = (int)((sqrtf(8.0f * pp + 1.0f) - 1.0f) * 0.5f);
        while ((ti + 1) * (ti + 2) / 2 <= pp) ++ti;
        while (ti * (ti + 1) / 2 > pp) --ti;
        tiR[r] = ti; tjR[r] = pp - ti * (ti + 1) / 2;
    }

    // ---- chunk loop: H = W W^T ----
    for (int c = 0; c < 2; c++) {
        const int base = c * CH;
        for (int idx = t; idx < 64 * 64; idx += NTH) {
            int a = idx >> 6, e = (idx & 63) * 4;
            float4 v  = *(const float4*)(Tm + a * NE + base + e);
            float4 s4 = *(const float4*)(sa + base + e);
            v.x *= s4.x; v.y *= s4.y; v.z *= s4.z; v.w *= s4.w;
            *(float4*)(Wc + a * WCP + e) = v;
        }
        if (t < 64) *(float4*)(Wc + 64 * WCP + 4*t) = *(const float4*)(sa + base + 4*t);
        __syncthreads();

        #pragma unroll
        for (int r = 0; r < 2; r++) {
            const float* Wa = Wc + (tiR[r] * 5) * WCP;
            const float* Wb = Wc + (tjR[r] * 5) * WCP;
            ull acc[25];
            #pragma unroll
            for (int m = 0; m < 25; m++) acc[m] = 0ull;
            for (int e = 4 * l8; e < CH; e += 32) {
                // LDS.128, conflict-free: each 8-lane phase = one l8-group,
                // 128B contiguous per row.
                ulonglong2 av[5];
                #pragma unroll
                for (int i = 0; i < 5; i++)
                    av[i] = *(const ulonglong2*)(Wa + i * WCP + e);
                #pragma unroll
                for (int j = 0; j < 5; j++) {
                    ulonglong2 bv = *(const ulonglong2*)(Wb + j * WCP + e);
                    #pragma unroll
                    for (int i = 0; i < 5; i++) {
                        acc[i*5+j] = ffma2(av[i].x, bv.x, acc[i*5+j]);
                        acc[i*5+j] = ffma2(av[i].y, bv.y, acc[i*5+j]);
                    }
                }
            }
            #pragma unroll
            for (int m = 0; m < 25; m++) {
                acc[m] = fadd2(acc[m], __shfl_down_sync(0xffffffffu, acc[m], 4));
                acc[m] = fadd2(acc[m], __shfl_down_sync(0xffffffffu, acc[m], 2));
                acc[m] = fadd2(acc[m], __shfl_down_sync(0xffffffffu, acc[m], 1));
            }
            if (actR[r] && l8 == 0) {
                int ti = tiR[r], tj = tjR[r];
                #pragma unroll
                for (int i = 0; i < 5; i++)
                    #pragma unroll
                    for (int j = 0; j < 5; j++) {
                        float2 f = unpack2(acc[i*5+j]);
                        float v = f.x + f.y;
                        int lo = (ti*5+i) * HP + (tj*5+j);
                        if (c == 0) Hs[lo] = v; else Hs[lo] += v;
                        if (ti != tj) {
                            int up = (tj*5+j) * HP + (ti*5+i);
                            if (c == 0) Hs[up] = v; else Hs[up] += v;
                        }
                    }
            }
        }
        __syncthreads();
    }

    // ---- K = I + H*C; rhs col 65 = -H*u (fp64); col 64 = delta - H col64 ----
    for (int a = w; a < NA; a += 12) {
        const float* Hr = Hs + a * HP;
        double acc = 0.0;
        for (int k2 = lane; k2 < NA; k2 += 32) {
            float uk = (k2 < 64) ? ens[k2] : q;
            acc += (double)Hr[k2] * (double)uk;
        }
        #pragma unroll
        for (int off = 16; off; off >>= 1) acc += __shfl_down_sync(0xffffffffu, acc, off);
        if (lane == 0) Km[a * KP + 65] = (float)(-acc);
    }
    if (t < NA)
        Km[t * KP + 64] = ((t == 64) ? 1.0f : 0.0f) - Hs[t * HP + 64];

    // K cols 0..63: half-warp per row a, lanes = 16 col-groups of 4.
    // A read as rows (contiguous in c) -> conflict-free; H[a][k] broadcast.
    {
        const int half = lane >> 4;       // 0/1
        const int c0 = (lane & 15) * 4;   // 0,4,...,60
        #pragma unroll
        for (int pass = 0; pass < 3; pass++) {
            int a = pass * 24 + w * 2 + half;
            if (a < NA) {
                const float* Hr = Hs + a * HP;
                ull acc0 = 0ull, acc1 = 0ull;
                #pragma unroll 4
                for (int k4 = 0; k4 < 16; k4++) {
                    float4 hv = *(const float4*)(Hr + k4 * 4);
                    ulonglong2 a0 = *(const ulonglong2*)(As + (k4*4+0) * 64 + c0);
                    ulonglong2 a1 = *(const ulonglong2*)(As + (k4*4+1) * 64 + c0);
                    ulonglong2 a2 = *(const ulonglong2*)(As + (k4*4+2) * 64 + c0);
                    ulonglong2 a3 = *(const ulonglong2*)(As + (k4*4+3) * 64 + c0);
                    ull h0 = dup2(hv.x), h1 = dup2(hv.y), h2 = dup2(hv.z), h3 = dup2(hv.w);
                    acc0 = ffma2(h0, a0.x, acc0); acc1 = ffma2(h0, a0.y, acc1);
                    acc0 = ffma2(h1, a1.x, acc0); acc1 = ffma2(h1, a1.y, acc1);
                    acc0 = ffma2(h2, a2.x, acc0); acc1 = ffma2(h2, a2.y, acc1);
                    acc0 = ffma2(h3, a3.x, acc0); acc1 = ffma2(h3, a3.y, acc1);
                }
                float2 f0 = unpack2(acc0), f1 = unpack2(acc1);
                float4 v;
                v.x = f0.x + ((a == c0+0) ? 1.0f : 0.0f);
                v.y = f0.y + ((a == c0+1) ? 1.0f : 0.0f);
                v.z = f1.x + ((a == c0+2) ? 1.0f : 0.0f);
                v.w = f1.y + ((a == c0+3) ? 1.0f : 0.0f);
                *(float4*)(Km + a * KP + c0) = v;   // KP=68 -> 16B-aligned rows
            }
        }
    }
    __syncthreads();

    // ---- Gauss-Jordan, register-resident columns, shfl pivot rows ----
    {
        const int cols0 = (w < 6) ? 6 : 5;     // cols 0..65: warps 0-5 own 6, 6-11 own 5
        float cv0[6], cv1[6], cv2[6];
        #pragma unroll
        for (int c = 0; c < 6; c++) {
            cv0[c] = 0.f; cv1[c] = 0.f; cv2[c] = 0.f;
            int j = w + 12 * c;
            if (c < cols0) {
                cv0[c] = Km[lane * KP + j];
                cv1[c] = Km[(lane + 32) * KP + j];
                if (lane == 0) cv2[c] = Km[64 * KP + j];
            }
        }
        bool piv0 = false, piv1 = false, piv2 = false;
        if (w == 0) {                           // publish col 0 + select pivot 0
            Fm[lane] = cv0[0];
            Fm[lane + 32] = cv1[0];
            if (lane == 0) Fm[64] = cv2[0];
            unsigned int key = pivkey(cv0[0], lane);
            unsigned int k1  = pivkey(cv1[0], lane + 32);
            if (k1 > key) key = k1;
            if (lane == 0) { unsigned int k2 = pivkey(cv2[0], 64); if (k2 > key) key = k2; }
            #pragma unroll
            for (int o = 16; o; o >>= 1) {
                unsigned int ov = __shfl_xor_sync(0xffffffffu, key, o);
                if (ov > key) key = ov;
            }
            int prow = (int)(key & 0x7Fu);
            float src = (prow < 32) ? cv0[0] : ((prow < 64) ? cv1[0] : cv2[0]);
            float pval = __shfl_sync(0xffffffffu, src, prow & 31);
            if (lane == 0) { pivhist[0] = prow; dinv[0] = 1.0f / pval; }
        }
        __syncthreads();

        for (int k = 0; k < NA; k++) {
            int pk = pivhist[k];
            float dk = dinv[k];
            float m0 = Fm[k * FP + lane] * dk;
            float m1 = Fm[k * FP + lane + 32] * dk;
            float m2 = Fm[k * FP + 64] * dk;
            if (lane == pk)      { m0 = 0.f; piv0 = true; }
            if (lane + 32 == pk) { m1 = 0.f; piv1 = true; }
            if (pk == 64)        { m2 = 0.f; piv2 = true; }
            #pragma unroll
            for (int c = 0; c < 6; c++) {
                int j = w + 12 * c;
                if (c < cols0 && j > k) {       // warp-uniform predicate
                    float src = (pk < 32) ? cv0[c] : ((pk < 64) ? cv1[c] : cv2[c]);
                    float pv = __shfl_sync(0xffffffffu, src, pk & 31);
                    cv0[c] = fmaf(-m0, pv, cv0[c]);
                    cv1[c] = fmaf(-m1, pv, cv1[c]);
                    cv2[c] = fmaf(-m2, pv, cv2[c]);
                }
            }
            int nk = k + 1;
            if (nk < NA && w == (nk % 12)) {    // publish col nk + select pivot nk
                #pragma unroll
                for (int c = 0; c < 6; c++) {
                    if (c < cols0 && (w + 12 * c) == nk) {
                        float v0 = cv0[c], v1 = cv1[c], v2 = cv2[c];
                        Fm[nk * FP + lane] = v0;
                        Fm[nk * FP + lane + 32] = v1;
                        if (lane == 0) Fm[nk * FP + 64] = v2;
                        unsigned int key = piv0 ? 0u : pivkey(v0, lane);
                        unsigned int k1  = piv1 ? 0u : pivkey(v1, lane + 32);
                        if (k1 > key) key = k1;
                        if (lane == 0 && !piv2) {
                            unsigned int k2 = pivkey(v2, 64);
                            if (k2 > key) key = k2;
                        }
                        #pragma unroll
                        for (int o = 16; o; o >>= 1) {
                            unsigned int ov = __shfl_xor_sync(0xffffffffu, key, o);
                            if (ov > key) key = ov;
                        }
                        int prow = (int)(key & 0x7Fu);
                        float src = (prow < 32) ? v0 : ((prow < 64) ? v1 : v2);
                        float pval = __shfl_sync(0xffffffffu, src, prow & 31);
                        if (lane == 0) { pivhist[nk] = prow; dinv[nk] = 1.0f / pval; }
                    }
                }
            }
            __syncthreads();
        }

        // rhs col 65 lives in warp 5 (c = 5): publish to rf
        if (w == 5) {
            rf[lane] = cv0[5];
            rf[lane + 32] = cv1[5];
            if (lane == 0) rf[64] = cv2[5];
        }
        __syncthreads();
    }

    // ---- direct solution (Jordan) ----
    if (t < NA) wd[t] = (double)(rf[pivhist[t]] * dinv[t]);
    __syncthreads();

    // ---- 1x fp64-residual refinement: rf = -w - H*(u + C*w) ----
    {
        for (int kk = w; kk < NAT; kk += 12) {
            const float* Ar = As + kk * 64;
            double acc = 0.0;
            for (int cc = lane; cc < NAT; cc += 32) acc += (double)Ar[cc] * wd[cc];
            #pragma unroll
            for (int off = 16; off; off >>= 1) acc += __shfl_down_sync(0xffffffffu, acc, off);
            if (lane == 0) cwd[kk] = acc;
        }
        if (t == 0) cwd[64] = -wd[64];
        __syncthreads();
        for (int a = w; a < NA; a += 12) {
            const float* Hr = Hs + a * HP;
            double acc = 0.0;
            for (int k2 = lane; k2 < NA; k2 += 32) {
                double uk = (k2 < 64) ? (double)ens[k2] : (double)q;
                acc += (double)Hr[k2] * (cwd[k2] + uk);
            }
            #pragma unroll
            for (int off = 16; off; off >>= 1) acc += __shfl_down_sync(0xffffffffu, acc, off);
            if (lane == 0) rf[a] = (float)(-wd[a] - acc);
        }
        __syncthreads();
        // apply Jordan factors (from Fm) to residual: register-resident, warp 0
        if (t < 32) {
            float r0 = rf[t];
            float r1 = rf[t + 32];
            float r2 = (t == 0) ? rf[64] : 0.f;
            for (int k = 0; k < NA; k++) {
                int pk = pivhist[k];
                float dk = dinv[k];
                float own = (pk < 32) ? r0 : ((pk < 64) ? r1 : r2);
                float xk = __shfl_sync(0xffffffffu, own, pk & 31);
                if (t != pk)      r0 = fmaf(-(Fm[k * FP + t] * dk), xk, r0);
                if (t + 32 != pk) r1 = fmaf(-(Fm[k * FP + t + 32] * dk), xk, r1);
                if (t == 0 && pk != 64) r2 = fmaf(-(Fm[k * FP + 64] * dk), xk, r2);
            }
            rg[t] = r0; rg[t + 32] = r1;
            if (t == 0) rg[64] = r2;
            __syncwarp();
            for (int i = t; i < NA; i += 32)
                wd[i] += (double)(rg[pivhist[i]] * dinv[i]);
        }
        __syncthreads();
    }

    // ---- output ----
    if (t < NAT) out[mol * NAT + t] = (float)wd[t];
}

extern "C" void kernel_launch(void* const* d_in, const int* in_sizes, int n_in,
                              void* d_out, int out_size)
{
    const float* positions      = (const float*)d_in[0];
    const float* T              = (const float*)d_in[1];
    const float* eneg           = (const float*)d_in[2];
    const float* node_attrs     = (const float*)d_in[3];
    const float* total_charge   = (const float*)d_in[4];
    const float* hardness       = (const float*)d_in[6];
    const float* cov_radii      = (const float*)d_in[7];
    const int*   atomic_numbers = (const int*)d_in[8];
    const int*   edge_index     = (const int*)d_in[9];
    float* out = (float*)d_out;

    int B = in_sizes[4];
    cudaFuncSetAttribute(cheq_kernel, cudaFuncAttributeMaxDynamicSharedMemorySize, SMEM_BYTES);
    cheq_kernel<<<B, NTH, SMEM_BYTES>>>(positions, T, eneg, node_attrs, total_charge,
                                        hardness, cov_radii, atomic_numbers, edge_index, out);
}